// round 2
// baseline (speedup 1.0000x reference)
#include <cuda_runtime.h>
#include <cuda_bf16.h>
#include <math.h>

#define TDIM 16384
#define CDIM 1024
#define WIN 32
#define DHEAD 64
#define NHEADS 16
#define QKVN 3072

// Scratch (device globals; no allocation allowed).
// g_buf holds `normed` (T,C) for the QKV GEMM, then is reused for the
// attention output (normed is dead by then).
__device__ float g_qkv[TDIM * QKVN];      // (T, 3C) 192 MB
__device__ float g_buf[TDIM * CDIM];      // (T, C)   64 MB

// ---------------------------------------------------------------------------
// Kernel 1: LayerNorm over channel dim. x is (C, T) channel-major.
// One block = 32 tokens. Two passes: stats, then normalize via 32x32 smem
// transpose chunks so both global read and write are coalesced.
// ---------------------------------------------------------------------------
__global__ void __launch_bounds__(256) ln_kernel(
    const float* __restrict__ x,
    const float* __restrict__ gamma,
    const float* __restrict__ beta,
    float* __restrict__ out)   // (T, C)
{
    const int t0 = blockIdx.x * WIN;
    const int tx = threadIdx.x & 31;   // token within window
    const int ty = threadIdx.x >> 5;   // 0..7

    __shared__ float rs[8][32];
    __shared__ float rs2[8][32];
    __shared__ float s_mu[32];
    __shared__ float s_rsig[32];
    __shared__ float tile[32][33];

    float s = 0.f, s2 = 0.f;
    const int t = t0 + tx;
    for (int c = ty; c < CDIM; c += 8) {
        float v = x[c * TDIM + t];
        s += v;
        s2 += v * v;
    }
    rs[ty][tx] = s;
    rs2[ty][tx] = s2;
    __syncthreads();
    if (ty == 0) {
        float a = 0.f, b = 0.f;
#pragma unroll
        for (int j = 0; j < 8; j++) { a += rs[j][tx]; b += rs2[j][tx]; }
        float mu = a * (1.0f / CDIM);
        float var = b * (1.0f / CDIM) - mu * mu;
        s_mu[tx] = mu;
        s_rsig[tx] = rsqrtf(var + 1e-5f);
    }
    __syncthreads();

    for (int c0 = 0; c0 < CDIM; c0 += 32) {
        for (int r = ty; r < 32; r += 8)
            tile[r][tx] = x[(c0 + r) * TDIM + t0 + tx];
        __syncthreads();
        float g = gamma[c0 + tx];
        float be = beta[c0 + tx];
        for (int tl = ty; tl < 32; tl += 8) {
            float v = tile[tx][tl];   // x[c0+tx][t0+tl]
            float val = (v - s_mu[tl]) * s_rsig[tl] * g + be;
            out[(t0 + tl) * CDIM + c0 + tx] = val;
        }
        __syncthreads();
    }
}

// ---------------------------------------------------------------------------
// Kernel 2/4: SGEMM  C[m][n] = sum_k A[m][k] * B[n][k]
//   A: (M, K) row-major, B: (N, K) row-major (weight layout (out,in))
// 128x128 block tile, Ktile=16, 256 threads, 8x8 register microtile,
// register-prefetch of the next K-tile overlapped with compute.
// TRANS_RESID epilogue: out[n*M + m] = acc + resid[n*M + m]
// ---------------------------------------------------------------------------
template <bool TRANS_RESID>
__global__ void __launch_bounds__(256) sgemm_kernel(
    const float* __restrict__ A,
    const float* __restrict__ B,
    float* __restrict__ Cmat,
    const float* __restrict__ resid,
    int M, int N, int K)
{
    __shared__ float As[16][132];
    __shared__ float Bs[16][132];

    const int bm = blockIdx.x * 128;
    const int bn = blockIdx.y * 128;
    const int tid = threadIdx.x;

    const int lrow = tid >> 2;       // 0..63
    const int lk4  = (tid & 3) * 4;  // 0,4,8,12

    const int ti = tid >> 4;         // 0..15 -> m rows ti*8..ti*8+7
    const int tj = tid & 15;         // 0..15 -> n cols tj*8..tj*8+7

    float acc[8][8];
#pragma unroll
    for (int i = 0; i < 8; i++)
#pragma unroll
        for (int j = 0; j < 8; j++) acc[i][j] = 0.f;

    float4 ra[2], rb[2];

    // Prologue: load K-tile 0 into registers, park in smem.
#pragma unroll
    for (int rr = 0; rr < 2; rr++) {
        ra[rr] = *(const float4*)&A[(long)(bm + lrow + rr * 64) * K + lk4];
        rb[rr] = *(const float4*)&B[(long)(bn + lrow + rr * 64) * K + lk4];
    }
#pragma unroll
    for (int rr = 0; rr < 2; rr++) {
        As[lk4 + 0][lrow + rr * 64] = ra[rr].x;
        As[lk4 + 1][lrow + rr * 64] = ra[rr].y;
        As[lk4 + 2][lrow + rr * 64] = ra[rr].z;
        As[lk4 + 3][lrow + rr * 64] = ra[rr].w;
        Bs[lk4 + 0][lrow + rr * 64] = rb[rr].x;
        Bs[lk4 + 1][lrow + rr * 64] = rb[rr].y;
        Bs[lk4 + 2][lrow + rr * 64] = rb[rr].z;
        Bs[lk4 + 3][lrow + rr * 64] = rb[rr].w;
    }
    __syncthreads();

    for (int k0 = 16; k0 <= K; k0 += 16) {
        const bool more = (k0 < K);
        // Prefetch next tile into registers (overlaps with FMA below).
        if (more) {
#pragma unroll
            for (int rr = 0; rr < 2; rr++) {
                ra[rr] = *(const float4*)&A[(long)(bm + lrow + rr * 64) * K + k0 + lk4];
                rb[rr] = *(const float4*)&B[(long)(bn + lrow + rr * 64) * K + k0 + lk4];
            }
        }

#pragma unroll
        for (int kk = 0; kk < 16; kk++) {
            float a[8], b[8];
#pragma unroll
            for (int i = 0; i < 8; i++) a[i] = As[kk][ti * 8 + i];
#pragma unroll
            for (int j = 0; j < 8; j++) b[j] = Bs[kk][tj * 8 + j];
#pragma unroll
            for (int i = 0; i < 8; i++)
#pragma unroll
                for (int j = 0; j < 8; j++) acc[i][j] = fmaf(a[i], b[j], acc[i][j]);
        }
        __syncthreads();

        if (more) {
#pragma unroll
            for (int rr = 0; rr < 2; rr++) {
                As[lk4 + 0][lrow + rr * 64] = ra[rr].x;
                As[lk4 + 1][lrow + rr * 64] = ra[rr].y;
                As[lk4 + 2][lrow + rr * 64] = ra[rr].z;
                As[lk4 + 3][lrow + rr * 64] = ra[rr].w;
                Bs[lk4 + 0][lrow + rr * 64] = rb[rr].x;
                Bs[lk4 + 1][lrow + rr * 64] = rb[rr].y;
                Bs[lk4 + 2][lrow + rr * 64] = rb[rr].z;
                Bs[lk4 + 3][lrow + rr * 64] = rb[rr].w;
            }
            __syncthreads();
        }
    }

    if (!TRANS_RESID) {
#pragma unroll
        for (int i = 0; i < 8; i++) {
            int m = bm + ti * 8 + i;
#pragma unroll
            for (int j = 0; j < 8; j++) {
                int n = bn + tj * 8 + j;
                Cmat[(long)m * N + n] = acc[i][j];
            }
        }
    } else {
        // out is (N, M): out[n][m] = acc + resid[n][m]
#pragma unroll
        for (int j = 0; j < 8; j++) {
            int n = bn + tj * 8 + j;
#pragma unroll
            for (int i = 0; i < 8; i++) {
                int m = bm + ti * 8 + i;
                long idx = (long)n * M + m;
                Cmat[idx] = acc[i][j] + resid[idx];
            }
        }
    }
}

// ---------------------------------------------------------------------------
// Kernel 3: per-(window, head) RoPE + full 32x32 attention.
// ---------------------------------------------------------------------------
__global__ void __launch_bounds__(256) attn_kernel(float* __restrict__ att)
{
    const int w = blockIdx.x;     // 0..511
    const int h = blockIdx.y;     // 0..15
    const int t0 = w * WIN;
    const int tid = threadIdx.x;

    __shared__ float qs[32][65];
    __shared__ float ks[32][65];
    __shared__ float vs[32][65];
    __shared__ float ls[32][33];

    const float LOG1E4 = 9.210340371976184f; // ln(10000)

    for (int e = tid; e < 32 * 64; e += 256) {
        int n = e >> 6;
        int d = e & 63;
        long row = (long)(t0 + n) * QKVN;
        float q = g_qkv[row + h * 64 + d];
        float k = g_qkv[row + 1024 + h * 64 + d];
        float v = g_qkv[row + 2048 + h * 64 + d];
        int j = d & 31;
        float inv = expf(-((float)j / 32.f) * LOG1E4);
        float ang = (float)n * inv;
        float sn, cs;
        sincosf(ang, &sn, &cs);
        float qr, kr;
        if (d < 32) {
            qr = -g_qkv[row + h * 64 + d + 32];
            kr = -g_qkv[row + 1024 + h * 64 + d + 32];
        } else {
            qr = g_qkv[row + h * 64 + d - 32];
            kr = g_qkv[row + 1024 + h * 64 + d - 32];
        }
        qs[n][d] = q * cs + qr * sn;
        ks[n][d] = k * cs + kr * sn;
        vs[n][d] = v;
    }
    __syncthreads();

    for (int e = tid; e < 32 * 32; e += 256) {
        int n = e >> 5;
        int m = e & 31;
        float a = 0.f;
#pragma unroll
        for (int d = 0; d < 64; d++) a = fmaf(qs[n][d], ks[m][d], a);
        ls[n][m] = a * 0.125f;   // 64^-0.5
    }
    __syncthreads();

    const int warp = tid >> 5, lane = tid & 31;
    for (int r = warp; r < 32; r += 8) {
        float v = ls[r][lane];
        float mx = v;
#pragma unroll
        for (int o = 16; o; o >>= 1) mx = fmaxf(mx, __shfl_xor_sync(0xffffffffu, mx, o));
        float ev = __expf(v - mx);
        float sm = ev;
#pragma unroll
        for (int o = 16; o; o >>= 1) sm += __shfl_xor_sync(0xffffffffu, sm, o);
        ls[r][lane] = ev / sm;
    }
    __syncthreads();

    for (int e = tid; e < 32 * 64; e += 256) {
        int n = e >> 6;
        int d = e & 63;
        float a = 0.f;
#pragma unroll
        for (int m = 0; m < 32; m++) a = fmaf(ls[n][m], vs[m][d], a);
        att[(long)(t0 + n) * CDIM + h * 64 + d] = a;
    }
}

// ---------------------------------------------------------------------------
extern "C" void kernel_launch(void* const* d_in, const int* in_sizes, int n_in,
                              void* d_out, int out_size)
{
    (void)in_sizes; (void)n_in; (void)out_size;
    const float* x     = (const float*)d_in[0];
    const float* wqkv  = (const float*)d_in[1];
    const float* wout  = (const float*)d_in[2];
    const float* gamma = (const float*)d_in[3];
    const float* beta  = (const float*)d_in[4];
    float* out = (float*)d_out;

    float *qkv, *buf;
    cudaGetSymbolAddress((void**)&qkv, g_qkv);
    cudaGetSymbolAddress((void**)&buf, g_buf);

    // 1. LayerNorm -> buf (= normed, (T, C))
    ln_kernel<<<TDIM / WIN, 256>>>(x, gamma, beta, buf);

    // 2. QKV GEMM: (T, C) x (3C, C)^T -> (T, 3C)
    sgemm_kernel<false><<<dim3(TDIM / 128, QKVN / 128), 256>>>(
        buf, wqkv, qkv, nullptr, TDIM, QKVN, CDIM);

    // 3. RoPE + windowed attention -> buf (= att, (T, C)); normed is dead.
    attn_kernel<<<dim3(TDIM / WIN, NHEADS), 256>>>(buf);

    // 4. Output GEMM + transposed residual epilogue -> d_out (C, T)
    sgemm_kernel<true><<<dim3(TDIM / 128, CDIM / 128), 256>>>(
        buf, wout, out, x, TDIM, CDIM, CDIM);
}

// round 5
// speedup vs baseline: 2.2677x; 2.2677x over previous
#include <cuda_runtime.h>
#include <cuda_bf16.h>
#include <math.h>
#include <stdint.h>

#define TDIM 16384
#define CDIM 1024
#define WIN 32
#define DHEAD 64
#define NHEADS 16
#define QKVN 3072

// Scratch (device globals; no allocation allowed).
__device__ float g_qkv[TDIM * QKVN];      // (T, 3C) 192 MB
__device__ float g_buf[TDIM * CDIM];      // (T, C)   64 MB  (normed, then att)

// ---------------------------------------------------------------------------
// PTX helpers
// ---------------------------------------------------------------------------
__device__ __forceinline__ uint32_t f2tf(float x) {
    uint32_t r;
    asm("cvt.rna.tf32.f32 %0, %1;" : "=r"(r) : "f"(x));
    return r;
}

__device__ __forceinline__ void mma_tf32(float* c, const uint32_t* a, const uint32_t* b) {
    asm volatile(
        "mma.sync.aligned.m16n8k8.row.col.f32.tf32.tf32.f32 "
        "{%0,%1,%2,%3}, {%4,%5,%6,%7}, {%8,%9}, {%0,%1,%2,%3};"
        : "+f"(c[0]), "+f"(c[1]), "+f"(c[2]), "+f"(c[3])
        : "r"(a[0]), "r"(a[1]), "r"(a[2]), "r"(a[3]), "r"(b[0]), "r"(b[1]));
}

// ---------------------------------------------------------------------------
// Kernel 1: LayerNorm over channel dim. x is (C, T). Output (T, C).
// ---------------------------------------------------------------------------
__global__ void __launch_bounds__(256) ln_kernel(
    const float* __restrict__ x,
    const float* __restrict__ gamma,
    const float* __restrict__ beta,
    float* __restrict__ out)
{
    const int t0 = blockIdx.x * WIN;
    const int tx = threadIdx.x & 31;
    const int ty = threadIdx.x >> 5;

    __shared__ float rs[8][32];
    __shared__ float rs2[8][32];
    __shared__ float s_mu[32];
    __shared__ float s_rsig[32];
    __shared__ float tile[32][33];

    float s = 0.f, s2 = 0.f;
    const int t = t0 + tx;
    for (int c = ty; c < CDIM; c += 8) {
        float v = x[c * TDIM + t];
        s += v; s2 += v * v;
    }
    rs[ty][tx] = s; rs2[ty][tx] = s2;
    __syncthreads();
    if (ty == 0) {
        float a = 0.f, b = 0.f;
#pragma unroll
        for (int j = 0; j < 8; j++) { a += rs[j][tx]; b += rs2[j][tx]; }
        float mu = a * (1.0f / CDIM);
        float var = b * (1.0f / CDIM) - mu * mu;
        s_mu[tx] = mu;
        s_rsig[tx] = rsqrtf(var + 1e-5f);
    }
    __syncthreads();

    for (int c0 = 0; c0 < CDIM; c0 += 32) {
        for (int r = ty; r < 32; r += 8)
            tile[r][tx] = x[(c0 + r) * TDIM + t0 + tx];
        __syncthreads();
        float g = gamma[c0 + tx];
        float be = beta[c0 + tx];
        for (int tl = ty; tl < 32; tl += 8) {
            float v = tile[tx][tl];
            out[(t0 + tl) * CDIM + c0 + tx] = (v - s_mu[tl]) * s_rsig[tl] * g + be;
        }
        __syncthreads();
    }
}

// ---------------------------------------------------------------------------
// TF32 tensor-core GEMM:  C[m][n] = sum_k A[m][k] * B[n][k]
//   A: (M,K) row-major, B: (N,K) row-major.
// 128x128 block tile, Ktile=16, 256 threads (8 warps, 2x4), warp tile 64x32,
// 4x4 m16n8k8 microtiles. Plain float4 global loads + register prefetch
// (the exact skeleton of the round-2 kernel that passed). Static smem only.
// TRANS_RESID: out[n*M+m] = acc + resid[n*M+m], staged 32 n-rows at a time.
// ---------------------------------------------------------------------------
#define KSTR 136                 // smem row stride (mod 32 == 8 -> conflict-free frags)

template <bool TRANS_RESID>
__global__ void __launch_bounds__(256) tgemm_kernel(
    const float* __restrict__ A,
    const float* __restrict__ B,
    float* __restrict__ Cmat,
    const float* __restrict__ resid,
    int M, int N, int K)
{
    __shared__ float sh[2 * 16 * KSTR];      // 17408 B, static
    float* As = sh;                          // [16][KSTR]  A[k][m]
    float* Bs = sh + 16 * KSTR;              // [16][KSTR]  B[k][n]

    const int bm = blockIdx.x * 128;
    const int bn = blockIdx.y * 128;
    const int tid = threadIdx.x;
    const int warp = tid >> 5;
    const int lane = tid & 31;
    const int g = lane >> 2;       // 0..7
    const int tig = lane & 3;      // 0..3
    const int wm = (warp & 1) * 64;
    const int wn = (warp >> 1) * 32;

    const int lrow = tid >> 2;       // 0..63
    const int lk4  = (tid & 3) * 4;  // 0,4,8,12

    float acc[4][4][4];
#pragma unroll
    for (int i = 0; i < 4; i++)
#pragma unroll
        for (int j = 0; j < 4; j++)
#pragma unroll
            for (int r = 0; r < 4; r++) acc[i][j][r] = 0.f;

    float4 ra[2], rb[2];

    // Prologue: K-tile 0 -> registers -> smem.
#pragma unroll
    for (int rr = 0; rr < 2; rr++) {
        ra[rr] = *(const float4*)&A[(long)(bm + lrow + rr * 64) * K + lk4];
        rb[rr] = *(const float4*)&B[(long)(bn + lrow + rr * 64) * K + lk4];
    }
#pragma unroll
    for (int rr = 0; rr < 2; rr++) {
        int m = lrow + rr * 64;
        As[(lk4 + 0) * KSTR + m] = ra[rr].x;
        As[(lk4 + 1) * KSTR + m] = ra[rr].y;
        As[(lk4 + 2) * KSTR + m] = ra[rr].z;
        As[(lk4 + 3) * KSTR + m] = ra[rr].w;
        Bs[(lk4 + 0) * KSTR + m] = rb[rr].x;
        Bs[(lk4 + 1) * KSTR + m] = rb[rr].y;
        Bs[(lk4 + 2) * KSTR + m] = rb[rr].z;
        Bs[(lk4 + 3) * KSTR + m] = rb[rr].w;
    }
    __syncthreads();

    for (int k0 = 16; k0 <= K; k0 += 16) {
        const bool more = (k0 < K);
        if (more) {
#pragma unroll
            for (int rr = 0; rr < 2; rr++) {
                ra[rr] = *(const float4*)&A[(long)(bm + lrow + rr * 64) * K + k0 + lk4];
                rb[rr] = *(const float4*)&B[(long)(bn + lrow + rr * 64) * K + k0 + lk4];
            }
        }

#pragma unroll
        for (int ks = 0; ks < 2; ks++) {
            const int kc = ks * 8 + tig;
            uint32_t af[4][4], bf[4][2];
#pragma unroll
            for (int mt = 0; mt < 4; mt++) {
                int r0 = wm + 16 * mt + g;
                af[mt][0] = f2tf(As[kc * KSTR + r0]);
                af[mt][1] = f2tf(As[kc * KSTR + r0 + 8]);
                af[mt][2] = f2tf(As[(kc + 4) * KSTR + r0]);
                af[mt][3] = f2tf(As[(kc + 4) * KSTR + r0 + 8]);
            }
#pragma unroll
            for (int nt = 0; nt < 4; nt++) {
                int n0 = wn + 8 * nt + g;
                bf[nt][0] = f2tf(Bs[kc * KSTR + n0]);
                bf[nt][1] = f2tf(Bs[(kc + 4) * KSTR + n0]);
            }
#pragma unroll
            for (int mt = 0; mt < 4; mt++)
#pragma unroll
                for (int nt = 0; nt < 4; nt++)
                    mma_tf32(acc[mt][nt], af[mt], bf[nt]);
        }
        __syncthreads();

        if (more) {
#pragma unroll
            for (int rr = 0; rr < 2; rr++) {
                int m = lrow + rr * 64;
                As[(lk4 + 0) * KSTR + m] = ra[rr].x;
                As[(lk4 + 1) * KSTR + m] = ra[rr].y;
                As[(lk4 + 2) * KSTR + m] = ra[rr].z;
                As[(lk4 + 3) * KSTR + m] = ra[rr].w;
                Bs[(lk4 + 0) * KSTR + m] = rb[rr].x;
                Bs[(lk4 + 1) * KSTR + m] = rb[rr].y;
                Bs[(lk4 + 2) * KSTR + m] = rb[rr].z;
                Bs[(lk4 + 3) * KSTR + m] = rb[rr].w;
            }
            __syncthreads();
        }
    }

    if (!TRANS_RESID) {
#pragma unroll
        for (int mt = 0; mt < 4; mt++) {
            int m = bm + wm + 16 * mt + g;
#pragma unroll
            for (int nt = 0; nt < 4; nt++) {
                int n = bn + wn + 8 * nt + 2 * tig;
                *(float2*)&Cmat[(long)m * N + n] =
                    make_float2(acc[mt][nt][0], acc[mt][nt][1]);
                *(float2*)&Cmat[(long)(m + 8) * N + n] =
                    make_float2(acc[mt][nt][2], acc[mt][nt][3]);
            }
        }
    } else {
        // out is (N, M). Stage 32 n-rows (one warp-pair's n-range) per pass in
        // smem transposed as Cs[n'][m], stride 132, then coalesced float4 out.
        float* Cs = sh;    // needs 32*132 = 4224 floats <= 4352 available
#pragma unroll
        for (int p = 0; p < 4; p++) {
            if ((warp >> 1) == p) {
#pragma unroll
                for (int mt = 0; mt < 4; mt++) {
                    int m = wm + 16 * mt + g;
#pragma unroll
                    for (int nt = 0; nt < 4; nt++) {
                        int np = 8 * nt + 2 * tig;   // n within this 32-chunk
                        Cs[np * 132 + m]           = acc[mt][nt][0];
                        Cs[(np + 1) * 132 + m]     = acc[mt][nt][1];
                        Cs[np * 132 + m + 8]       = acc[mt][nt][2];
                        Cs[(np + 1) * 132 + m + 8] = acc[mt][nt][3];
                    }
                }
            }
            __syncthreads();
#pragma unroll
            for (int i = 0; i < 4; i++) {
                int idx = tid + 256 * i;          // 0..1023
                int row = idx >> 5;               // 0..31
                int m4 = (idx & 31) * 4;
                float4 c = *(float4*)&Cs[row * 132 + m4];
                long o = (long)(bn + p * 32 + row) * M + bm + m4;
                float4 r = *(const float4*)&resid[o];
                c.x += r.x; c.y += r.y; c.z += r.z; c.w += r.w;
                *(float4*)&Cmat[o] = c;
            }
            __syncthreads();
        }
    }
}

// ---------------------------------------------------------------------------
// Kernel 3: per-(window, head) RoPE + full 32x32 attention.
// ---------------------------------------------------------------------------
__global__ void __launch_bounds__(256) attn_kernel(float* __restrict__ att)
{
    const int w = blockIdx.x;
    const int h = blockIdx.y;
    const int t0 = w * WIN;
    const int tid = threadIdx.x;

    __shared__ float qs[32][65];
    __shared__ float ks[32][65];
    __shared__ float vs[32][65];
    __shared__ float ls[32][33];

    const float LOG1E4 = 9.210340371976184f;

    for (int e = tid; e < 32 * 64; e += 256) {
        int n = e >> 6;
        int d = e & 63;
        long row = (long)(t0 + n) * QKVN;
        float q = g_qkv[row + h * 64 + d];
        float k = g_qkv[row + 1024 + h * 64 + d];
        float v = g_qkv[row + 2048 + h * 64 + d];
        int j = d & 31;
        float inv = expf(-((float)j / 32.f) * LOG1E4);
        float ang = (float)n * inv;
        float sn, cs;
        sincosf(ang, &sn, &cs);
        float qr, kr;
        if (d < 32) {
            qr = -g_qkv[row + h * 64 + d + 32];
            kr = -g_qkv[row + 1024 + h * 64 + d + 32];
        } else {
            qr = g_qkv[row + h * 64 + d - 32];
            kr = g_qkv[row + 1024 + h * 64 + d - 32];
        }
        qs[n][d] = q * cs + qr * sn;
        ks[n][d] = k * cs + kr * sn;
        vs[n][d] = v;
    }
    __syncthreads();

    for (int e = tid; e < 32 * 32; e += 256) {
        int n = e >> 5;
        int m = e & 31;
        float a = 0.f;
#pragma unroll
        for (int d = 0; d < 64; d++) a = fmaf(qs[n][d], ks[m][d], a);
        ls[n][m] = a * 0.125f;
    }
    __syncthreads();

    const int warp = tid >> 5, lane = tid & 31;
    for (int r = warp; r < 32; r += 8) {
        float v = ls[r][lane];
        float mx = v;
#pragma unroll
        for (int o = 16; o; o >>= 1) mx = fmaxf(mx, __shfl_xor_sync(0xffffffffu, mx, o));
        float ev = __expf(v - mx);
        float sm = ev;
#pragma unroll
        for (int o = 16; o; o >>= 1) sm += __shfl_xor_sync(0xffffffffu, sm, o);
        ls[r][lane] = ev / sm;
    }
    __syncthreads();

    for (int e = tid; e < 32 * 64; e += 256) {
        int n = e >> 6;
        int d = e & 63;
        float a = 0.f;
#pragma unroll
        for (int m = 0; m < 32; m++) a = fmaf(ls[n][m], vs[m][d], a);
        att[(long)(t0 + n) * CDIM + h * 64 + d] = a;
    }
}

// ---------------------------------------------------------------------------
extern "C" void kernel_launch(void* const* d_in, const int* in_sizes, int n_in,
                              void* d_out, int out_size)
{
    (void)in_sizes; (void)n_in; (void)out_size;
    const float* x     = (const float*)d_in[0];
    const float* wqkv  = (const float*)d_in[1];
    const float* wout  = (const float*)d_in[2];
    const float* gamma = (const float*)d_in[3];
    const float* beta  = (const float*)d_in[4];
    float* out = (float*)d_out;

    float *qkv, *buf;
    cudaGetSymbolAddress((void**)&qkv, g_qkv);
    cudaGetSymbolAddress((void**)&buf, g_buf);

    // 1. LayerNorm -> buf (= normed, (T, C))
    ln_kernel<<<TDIM / WIN, 256>>>(x, gamma, beta, buf);

    // 2. QKV GEMM: (T, C) x (3C, C)^T -> (T, 3C)
    tgemm_kernel<false><<<dim3(TDIM / 128, QKVN / 128), 256>>>(
        buf, wqkv, qkv, nullptr, TDIM, QKVN, CDIM);

    // 3. RoPE + windowed attention -> buf (= att, (T, C))
    attn_kernel<<<dim3(TDIM / WIN, NHEADS), 256>>>(buf);

    // 4. Output GEMM + transposed residual epilogue -> d_out (C, T)
    tgemm_kernel<true><<<dim3(TDIM / 128, CDIM / 128), 256>>>(
        buf, wout, out, x, TDIM, CDIM, CDIM);
}

// round 8
// speedup vs baseline: 2.2901x; 1.0099x over previous
#include <cuda_runtime.h>
#include <cuda_bf16.h>
#include <math.h>
#include <stdint.h>

#define TDIM 16384
#define CDIM 1024
#define WIN 32
#define DHEAD 64
#define NHEADS 16
#define QKVN 3072

// Scratch (device globals; no allocation allowed).
__device__ float g_qkv[TDIM * QKVN];      // (T, 3C) 192 MB
__device__ float g_buf[TDIM * CDIM];      // (T, C)   64 MB  (normed, then att)

// ---------------------------------------------------------------------------
// PTX helpers
// ---------------------------------------------------------------------------
__device__ __forceinline__ uint32_t f2tf(float x) {
    uint32_t r;
    asm("cvt.rna.tf32.f32 %0, %1;" : "=r"(r) : "f"(x));
    return r;
}

__device__ __forceinline__ void mma_tf32(float* c, const uint32_t* a, const uint32_t* b) {
    asm volatile(
        "mma.sync.aligned.m16n8k8.row.col.f32.tf32.tf32.f32 "
        "{%0,%1,%2,%3}, {%4,%5,%6,%7}, {%8,%9}, {%0,%1,%2,%3};"
        : "+f"(c[0]), "+f"(c[1]), "+f"(c[2]), "+f"(c[3])
        : "r"(a[0]), "r"(a[1]), "r"(a[2]), "r"(a[3]), "r"(b[0]), "r"(b[1]));
}

// ---------------------------------------------------------------------------
// Kernel 1: LayerNorm over channel dim. x is (C, T). Output (T, C).
// ---------------------------------------------------------------------------
__global__ void __launch_bounds__(256) ln_kernel(
    const float* __restrict__ x,
    const float* __restrict__ gamma,
    const float* __restrict__ beta,
    float* __restrict__ out)
{
    const int t0 = blockIdx.x * WIN;
    const int tx = threadIdx.x & 31;
    const int ty = threadIdx.x >> 5;

    __shared__ float rs[8][32];
    __shared__ float rs2[8][32];
    __shared__ float s_mu[32];
    __shared__ float s_rsig[32];
    __shared__ float tile[32][33];

    float s = 0.f, s2 = 0.f;
    const int t = t0 + tx;
    for (int c = ty; c < CDIM; c += 8) {
        float v = x[c * TDIM + t];
        s += v; s2 += v * v;
    }
    rs[ty][tx] = s; rs2[ty][tx] = s2;
    __syncthreads();
    if (ty == 0) {
        float a = 0.f, b = 0.f;
#pragma unroll
        for (int j = 0; j < 8; j++) { a += rs[j][tx]; b += rs2[j][tx]; }
        float mu = a * (1.0f / CDIM);
        float var = b * (1.0f / CDIM) - mu * mu;
        s_mu[tx] = mu;
        s_rsig[tx] = rsqrtf(var + 1e-5f);
    }
    __syncthreads();

    for (int c0 = 0; c0 < CDIM; c0 += 32) {
        for (int r = ty; r < 32; r += 8)
            tile[r][tx] = x[(c0 + r) * TDIM + t0 + tx];
        __syncthreads();
        float g = gamma[c0 + tx];
        float be = beta[c0 + tx];
        for (int tl = ty; tl < 32; tl += 8) {
            float v = tile[tx][tl];
            out[(t0 + tl) * CDIM + c0 + tx] = (v - s_mu[tl]) * s_rsig[tl] * g + be;
        }
        __syncthreads();
    }
}

// ---------------------------------------------------------------------------
// TF32 tensor-core GEMM:  C[m][n] = sum_k A[m][k] * B[n][k]
//   A: (M,K) row-major, B: (N,K) row-major.
// 128x128 block tile, Ktile=16, 256 threads (8 warps, 2x4), warp tile 64x32,
// 4x4 m16n8k8 microtiles. Smem holds PRE-CONVERTED tf32 bits (cvt hoisted to
// the STS stage: 8 cvt/thread/ktile instead of 48); inner loop is raw LDS.
// Plain float4 global loads + register prefetch, static smem, single buffer —
// byte-identical skeleton to the kernel that passed at 1683.6us.
// TRANS_RESID: out[n*M+m] = acc + resid[n*M+m], staged 32 n-rows at a time.
// ---------------------------------------------------------------------------
#define KSTR 136                 // smem row stride (mod 32 == 8 -> conflict-free frags)

template <bool TRANS_RESID>
__global__ void __launch_bounds__(256) tgemm_kernel(
    const float* __restrict__ A,
    const float* __restrict__ B,
    float* __restrict__ Cmat,
    const float* __restrict__ resid,
    int M, int N, int K)
{
    __shared__ uint32_t sh[2 * 16 * KSTR];   // 17408 B, static (tf32 bits)
    uint32_t* As = sh;                       // [16][KSTR]  A[k][m]
    uint32_t* Bs = sh + 16 * KSTR;           // [16][KSTR]  B[k][n]

    const int bm = blockIdx.x * 128;
    const int bn = blockIdx.y * 128;
    const int tid = threadIdx.x;
    const int warp = tid >> 5;
    const int lane = tid & 31;
    const int g = lane >> 2;       // 0..7
    const int tig = lane & 3;      // 0..3
    const int wm = (warp & 1) * 64;
    const int wn = (warp >> 1) * 32;

    const int lrow = tid >> 2;       // 0..63
    const int lk4  = (tid & 3) * 4;  // 0,4,8,12

    float acc[4][4][4];
#pragma unroll
    for (int i = 0; i < 4; i++)
#pragma unroll
        for (int j = 0; j < 4; j++)
#pragma unroll
            for (int r = 0; r < 4; r++) acc[i][j][r] = 0.f;

    float4 ra[2], rb[2];

    // Prologue: K-tile 0 -> registers -> cvt -> smem.
#pragma unroll
    for (int rr = 0; rr < 2; rr++) {
        ra[rr] = *(const float4*)&A[(long)(bm + lrow + rr * 64) * K + lk4];
        rb[rr] = *(const float4*)&B[(long)(bn + lrow + rr * 64) * K + lk4];
    }
#pragma unroll
    for (int rr = 0; rr < 2; rr++) {
        int m = lrow + rr * 64;
        As[(lk4 + 0) * KSTR + m] = f2tf(ra[rr].x);
        As[(lk4 + 1) * KSTR + m] = f2tf(ra[rr].y);
        As[(lk4 + 2) * KSTR + m] = f2tf(ra[rr].z);
        As[(lk4 + 3) * KSTR + m] = f2tf(ra[rr].w);
        Bs[(lk4 + 0) * KSTR + m] = f2tf(rb[rr].x);
        Bs[(lk4 + 1) * KSTR + m] = f2tf(rb[rr].y);
        Bs[(lk4 + 2) * KSTR + m] = f2tf(rb[rr].z);
        Bs[(lk4 + 3) * KSTR + m] = f2tf(rb[rr].w);
    }
    __syncthreads();

    for (int k0 = 16; k0 <= K; k0 += 16) {
        const bool more = (k0 < K);
        if (more) {
#pragma unroll
            for (int rr = 0; rr < 2; rr++) {
                ra[rr] = *(const float4*)&A[(long)(bm + lrow + rr * 64) * K + k0 + lk4];
                rb[rr] = *(const float4*)&B[(long)(bn + lrow + rr * 64) * K + k0 + lk4];
            }
        }

#pragma unroll
        for (int ks = 0; ks < 2; ks++) {
            const int kc = ks * 8 + tig;
            uint32_t af[4][4], bf[4][2];
#pragma unroll
            for (int mt = 0; mt < 4; mt++) {
                int r0 = wm + 16 * mt + g;
                af[mt][0] = As[kc * KSTR + r0];
                af[mt][1] = As[kc * KSTR + r0 + 8];
                af[mt][2] = As[(kc + 4) * KSTR + r0];
                af[mt][3] = As[(kc + 4) * KSTR + r0 + 8];
            }
#pragma unroll
            for (int nt = 0; nt < 4; nt++) {
                int n0 = wn + 8 * nt + g;
                bf[nt][0] = Bs[kc * KSTR + n0];
                bf[nt][1] = Bs[(kc + 4) * KSTR + n0];
            }
#pragma unroll
            for (int mt = 0; mt < 4; mt++)
#pragma unroll
                for (int nt = 0; nt < 4; nt++)
                    mma_tf32(acc[mt][nt], af[mt], bf[nt]);
        }
        __syncthreads();

        if (more) {
#pragma unroll
            for (int rr = 0; rr < 2; rr++) {
                int m = lrow + rr * 64;
                As[(lk4 + 0) * KSTR + m] = f2tf(ra[rr].x);
                As[(lk4 + 1) * KSTR + m] = f2tf(ra[rr].y);
                As[(lk4 + 2) * KSTR + m] = f2tf(ra[rr].z);
                As[(lk4 + 3) * KSTR + m] = f2tf(ra[rr].w);
                Bs[(lk4 + 0) * KSTR + m] = f2tf(rb[rr].x);
                Bs[(lk4 + 1) * KSTR + m] = f2tf(rb[rr].y);
                Bs[(lk4 + 2) * KSTR + m] = f2tf(rb[rr].z);
                Bs[(lk4 + 3) * KSTR + m] = f2tf(rb[rr].w);
            }
            __syncthreads();
        }
    }

    if (!TRANS_RESID) {
#pragma unroll
        for (int mt = 0; mt < 4; mt++) {
            int m = bm + wm + 16 * mt + g;
#pragma unroll
            for (int nt = 0; nt < 4; nt++) {
                int n = bn + wn + 8 * nt + 2 * tig;
                *(float2*)&Cmat[(long)m * N + n] =
                    make_float2(acc[mt][nt][0], acc[mt][nt][1]);
                *(float2*)&Cmat[(long)(m + 8) * N + n] =
                    make_float2(acc[mt][nt][2], acc[mt][nt][3]);
            }
        }
    } else {
        // out is (N, M). Stage 32 n-rows (one warp-pair's n-range) per pass in
        // smem transposed as Cs[n'][m], stride 132, then coalesced float4 out.
        float* Cs = (float*)sh;    // needs 32*132 = 4224 floats <= 4352 available
#pragma unroll
        for (int p = 0; p < 4; p++) {
            if ((warp >> 1) == p) {
#pragma unroll
                for (int mt = 0; mt < 4; mt++) {
                    int m = wm + 16 * mt + g;
#pragma unroll
                    for (int nt = 0; nt < 4; nt++) {
                        int np = 8 * nt + 2 * tig;   // n within this 32-chunk
                        Cs[np * 132 + m]           = acc[mt][nt][0];
                        Cs[(np + 1) * 132 + m]     = acc[mt][nt][1];
                        Cs[np * 132 + m + 8]       = acc[mt][nt][2];
                        Cs[(np + 1) * 132 + m + 8] = acc[mt][nt][3];
                    }
                }
            }
            __syncthreads();
#pragma unroll
            for (int i = 0; i < 4; i++) {
                int idx = tid + 256 * i;          // 0..1023
                int row = idx >> 5;               // 0..31
                int m4 = (idx & 31) * 4;
                float4 c = *(float4*)&Cs[row * 132 + m4];
                long o = (long)(bn + p * 32 + row) * M + bm + m4;
                float4 r = *(const float4*)&resid[o];
                c.x += r.x; c.y += r.y; c.z += r.z; c.w += r.w;
                *(float4*)&Cmat[o] = c;
            }
            __syncthreads();
        }
    }
}

// ---------------------------------------------------------------------------
// Kernel 3: per-(window, head) RoPE + full 32x32 attention.
// ---------------------------------------------------------------------------
__global__ void __launch_bounds__(256) attn_kernel(float* __restrict__ att)
{
    const int w = blockIdx.x;
    const int h = blockIdx.y;
    const int t0 = w * WIN;
    const int tid = threadIdx.x;

    __shared__ float qs[32][65];
    __shared__ float ks[32][65];
    __shared__ float vs[32][65];
    __shared__ float ls[32][33];

    const float LOG1E4 = 9.210340371976184f;

    for (int e = tid; e < 32 * 64; e += 256) {
        int n = e >> 6;
        int d = e & 63;
        long row = (long)(t0 + n) * QKVN;
        float q = g_qkv[row + h * 64 + d];
        float k = g_qkv[row + 1024 + h * 64 + d];
        float v = g_qkv[row + 2048 + h * 64 + d];
        int j = d & 31;
        float inv = expf(-((float)j / 32.f) * LOG1E4);
        float ang = (float)n * inv;
        float sn, cs;
        sincosf(ang, &sn, &cs);
        float qr, kr;
        if (d < 32) {
            qr = -g_qkv[row + h * 64 + d + 32];
            kr = -g_qkv[row + 1024 + h * 64 + d + 32];
        } else {
            qr = g_qkv[row + h * 64 + d - 32];
            kr = g_qkv[row + 1024 + h * 64 + d - 32];
        }
        qs[n][d] = q * cs + qr * sn;
        ks[n][d] = k * cs + kr * sn;
        vs[n][d] = v;
    }
    __syncthreads();

    for (int e = tid; e < 32 * 32; e += 256) {
        int n = e >> 5;
        int m = e & 31;
        float a = 0.f;
#pragma unroll
        for (int d = 0; d < 64; d++) a = fmaf(qs[n][d], ks[m][d], a);
        ls[n][m] = a * 0.125f;
    }
    __syncthreads();

    const int warp = tid >> 5, lane = tid & 31;
    for (int r = warp; r < 32; r += 8) {
        float v = ls[r][lane];
        float mx = v;
#pragma unroll
        for (int o = 16; o; o >>= 1) mx = fmaxf(mx, __shfl_xor_sync(0xffffffffu, mx, o));
        float ev = __expf(v - mx);
        float sm = ev;
#pragma unroll
        for (int o = 16; o; o >>= 1) sm += __shfl_xor_sync(0xffffffffu, sm, o);
        ls[r][lane] = ev / sm;
    }
    __syncthreads();

    for (int e = tid; e < 32 * 64; e += 256) {
        int n = e >> 6;
        int d = e & 63;
        float a = 0.f;
#pragma unroll
        for (int m = 0; m < 32; m++) a = fmaf(ls[n][m], vs[m][d], a);
        att[(long)(t0 + n) * CDIM + h * 64 + d] = a;
    }
}

// ---------------------------------------------------------------------------
extern "C" void kernel_launch(void* const* d_in, const int* in_sizes, int n_in,
                              void* d_out, int out_size)
{
    (void)in_sizes; (void)n_in; (void)out_size;
    const float* x     = (const float*)d_in[0];
    const float* wqkv  = (const float*)d_in[1];
    const float* wout  = (const float*)d_in[2];
    const float* gamma = (const float*)d_in[3];
    const float* beta  = (const float*)d_in[4];
    float* out = (float*)d_out;

    float *qkv, *buf;
    cudaGetSymbolAddress((void**)&qkv, g_qkv);
    cudaGetSymbolAddress((void**)&buf, g_buf);

    // 1. LayerNorm -> buf (= normed, (T, C))
    ln_kernel<<<TDIM / WIN, 256>>>(x, gamma, beta, buf);

    // 2. QKV GEMM: (T, C) x (3C, C)^T -> (T, 3C)
    tgemm_kernel<false><<<dim3(TDIM / 128, QKVN / 128), 256>>>(
        buf, wqkv, qkv, nullptr, TDIM, QKVN, CDIM);

    // 3. RoPE + windowed attention -> buf (= att, (T, C))
    attn_kernel<<<dim3(TDIM / WIN, NHEADS), 256>>>(buf);

    // 4. Output GEMM + transposed residual epilogue -> d_out (C, T)
    tgemm_kernel<true><<<dim3(TDIM / 128, CDIM / 128), 256>>>(
        buf, wout, out, x, TDIM, CDIM, CDIM);
}

// round 9
// speedup vs baseline: 3.2308x; 1.4108x over previous
#include <cuda_runtime.h>
#include <cuda_fp16.h>
#include <cuda_bf16.h>
#include <math.h>
#include <stdint.h>

#define TDIM 16384
#define CDIM 1024
#define WIN 32
#define DHEAD 64
#define NHEADS 16
#define QKVN 3072

// Scratch (device globals; no allocation allowed).
__device__ float g_qkv[TDIM * QKVN];      // (T, 3C) 192 MB
__device__ float g_buf[TDIM * CDIM];      // (T, C)   64 MB  (normed, then att)

// ---------------------------------------------------------------------------
// PTX helpers
// ---------------------------------------------------------------------------
__device__ __forceinline__ void mma_f16(float* c, const uint32_t* a, const uint32_t* b) {
    asm volatile(
        "mma.sync.aligned.m16n8k16.row.col.f32.f16.f16.f32 "
        "{%0,%1,%2,%3}, {%4,%5,%6,%7}, {%8,%9}, {%0,%1,%2,%3};"
        : "+f"(c[0]), "+f"(c[1]), "+f"(c[2]), "+f"(c[3])
        : "r"(a[0]), "r"(a[1]), "r"(a[2]), "r"(a[3]), "r"(b[0]), "r"(b[1]));
}

__device__ __forceinline__ uint32_t pack_h2(float x, float y) {
    __half2 h = __floats2half2_rn(x, y);
    return *(uint32_t*)&h;
}

// ---------------------------------------------------------------------------
// Kernel 1: LayerNorm over channel dim. x is (C, T). Output (T, C).
// ---------------------------------------------------------------------------
__global__ void __launch_bounds__(256) ln_kernel(
    const float* __restrict__ x,
    const float* __restrict__ gamma,
    const float* __restrict__ beta,
    float* __restrict__ out)
{
    const int t0 = blockIdx.x * WIN;
    const int tx = threadIdx.x & 31;
    const int ty = threadIdx.x >> 5;

    __shared__ float rs[8][32];
    __shared__ float rs2[8][32];
    __shared__ float s_mu[32];
    __shared__ float s_rsig[32];
    __shared__ float tile[32][33];

    float s = 0.f, s2 = 0.f;
    const int t = t0 + tx;
    for (int c = ty; c < CDIM; c += 8) {
        float v = x[c * TDIM + t];
        s += v; s2 += v * v;
    }
    rs[ty][tx] = s; rs2[ty][tx] = s2;
    __syncthreads();
    if (ty == 0) {
        float a = 0.f, b = 0.f;
#pragma unroll
        for (int j = 0; j < 8; j++) { a += rs[j][tx]; b += rs2[j][tx]; }
        float mu = a * (1.0f / CDIM);
        float var = b * (1.0f / CDIM) - mu * mu;
        s_mu[tx] = mu;
        s_rsig[tx] = rsqrtf(var + 1e-5f);
    }
    __syncthreads();

    for (int c0 = 0; c0 < CDIM; c0 += 32) {
        for (int r = ty; r < 32; r += 8)
            tile[r][tx] = x[(c0 + r) * TDIM + t0 + tx];
        __syncthreads();
        float g = gamma[c0 + tx];
        float be = beta[c0 + tx];
        for (int tl = ty; tl < 32; tl += 8) {
            float v = tile[tx][tl];
            out[(t0 + tl) * CDIM + c0 + tx] = (v - s_mu[tl]) * s_rsig[tl] * g + be;
        }
        __syncthreads();
    }
}

// ---------------------------------------------------------------------------
// FP16 tensor-core GEMM (f32 accumulate):  C[m][n] = sum_k A[m][k] * B[n][k]
//   A: (M,K) row-major fp32, B: (N,K) row-major fp32; converted to fp16 at STS.
// 128x128 block tile, Ktile=16, 256 threads (8 warps, 2x4), warp tile 64x32,
// 4x4 m16n8k16 microtiles (one per ktile). Smem is m-major fp16 [row][k],
// row stride 72 halves (144 B): /4 == 36 == 4 mod 32 -> fragment LDS hits
// banks 4g+tig (conflict-free). Register prefetch + single buffer, static
// smem — the twice-proven skeleton. Epilogues identical to the tf32 version.
// TRANS_RESID: out[n*M+m] = acc + resid[n*M+m], staged 32 n-rows at a time.
// ---------------------------------------------------------------------------
#define KSH 72                   // halves per smem row (144 B)

template <bool TRANS_RESID>
__global__ void __launch_bounds__(256) tgemm_kernel(
    const float* __restrict__ A,
    const float* __restrict__ B,
    float* __restrict__ Cmat,
    const float* __restrict__ resid,
    int M, int N, int K)
{
    __shared__ __align__(16) __half sh[2 * 128 * KSH];   // 36864 B, static
    __half* As = sh;                                     // [128][KSH]  A[m][k]
    __half* Bs = sh + 128 * KSH;                         // [128][KSH]  B[n][k]

    const int bm = blockIdx.x * 128;
    const int bn = blockIdx.y * 128;
    const int tid = threadIdx.x;
    const int warp = tid >> 5;
    const int lane = tid & 31;
    const int g = lane >> 2;       // 0..7
    const int tig = lane & 3;      // 0..3
    const int wm = (warp & 1) * 64;
    const int wn = (warp >> 1) * 32;

    const int lrow = tid >> 2;       // 0..63
    const int lk4  = (tid & 3) * 4;  // 0,4,8,12

    float acc[4][4][4];
#pragma unroll
    for (int i = 0; i < 4; i++)
#pragma unroll
        for (int j = 0; j < 4; j++)
#pragma unroll
            for (int r = 0; r < 4; r++) acc[i][j][r] = 0.f;

    float4 ra[2], rb[2];

    // Prologue: K-tile 0 -> registers -> fp16 -> smem.
#pragma unroll
    for (int rr = 0; rr < 2; rr++) {
        ra[rr] = *(const float4*)&A[(long)(bm + lrow + rr * 64) * K + lk4];
        rb[rr] = *(const float4*)&B[(long)(bn + lrow + rr * 64) * K + lk4];
    }
#pragma unroll
    for (int rr = 0; rr < 2; rr++) {
        int m = lrow + rr * 64;
        *(uint2*)&As[m * KSH + lk4] =
            make_uint2(pack_h2(ra[rr].x, ra[rr].y), pack_h2(ra[rr].z, ra[rr].w));
        *(uint2*)&Bs[m * KSH + lk4] =
            make_uint2(pack_h2(rb[rr].x, rb[rr].y), pack_h2(rb[rr].z, rb[rr].w));
    }
    __syncthreads();

    for (int k0 = 16; k0 <= K; k0 += 16) {
        const bool more = (k0 < K);
        if (more) {
#pragma unroll
            for (int rr = 0; rr < 2; rr++) {
                ra[rr] = *(const float4*)&A[(long)(bm + lrow + rr * 64) * K + k0 + lk4];
                rb[rr] = *(const float4*)&B[(long)(bn + lrow + rr * 64) * K + k0 + lk4];
            }
        }

        {
            const int kc = 2 * tig;           // half index within ktile
            uint32_t af[4][4], bf[4][2];
#pragma unroll
            for (int mt = 0; mt < 4; mt++) {
                int r0 = wm + 16 * mt + g;
                af[mt][0] = *(const uint32_t*)&As[r0 * KSH + kc];
                af[mt][1] = *(const uint32_t*)&As[(r0 + 8) * KSH + kc];
                af[mt][2] = *(const uint32_t*)&As[r0 * KSH + kc + 8];
                af[mt][3] = *(const uint32_t*)&As[(r0 + 8) * KSH + kc + 8];
            }
#pragma unroll
            for (int nt = 0; nt < 4; nt++) {
                int n0 = wn + 8 * nt + g;
                bf[nt][0] = *(const uint32_t*)&Bs[n0 * KSH + kc];
                bf[nt][1] = *(const uint32_t*)&Bs[n0 * KSH + kc + 8];
            }
#pragma unroll
            for (int mt = 0; mt < 4; mt++)
#pragma unroll
                for (int nt = 0; nt < 4; nt++)
                    mma_f16(acc[mt][nt], af[mt], bf[nt]);
        }
        __syncthreads();

        if (more) {
#pragma unroll
            for (int rr = 0; rr < 2; rr++) {
                int m = lrow + rr * 64;
                *(uint2*)&As[m * KSH + lk4] =
                    make_uint2(pack_h2(ra[rr].x, ra[rr].y), pack_h2(ra[rr].z, ra[rr].w));
                *(uint2*)&Bs[m * KSH + lk4] =
                    make_uint2(pack_h2(rb[rr].x, rb[rr].y), pack_h2(rb[rr].z, rb[rr].w));
            }
            __syncthreads();
        }
    }

    if (!TRANS_RESID) {
#pragma unroll
        for (int mt = 0; mt < 4; mt++) {
            int m = bm + wm + 16 * mt + g;
#pragma unroll
            for (int nt = 0; nt < 4; nt++) {
                int n = bn + wn + 8 * nt + 2 * tig;
                *(float2*)&Cmat[(long)m * N + n] =
                    make_float2(acc[mt][nt][0], acc[mt][nt][1]);
                *(float2*)&Cmat[(long)(m + 8) * N + n] =
                    make_float2(acc[mt][nt][2], acc[mt][nt][3]);
            }
        }
    } else {
        // out is (N, M). Stage 32 n-rows (one warp-pair's n-range) per pass in
        // smem transposed as Cs[n'][m], stride 132, then coalesced float4 out.
        float* Cs = (float*)sh;    // 32*132*4 = 16896 B <= 36864
#pragma unroll
        for (int p = 0; p < 4; p++) {
            if ((warp >> 1) == p) {
#pragma unroll
                for (int mt = 0; mt < 4; mt++) {
                    int m = wm + 16 * mt + g;
#pragma unroll
                    for (int nt = 0; nt < 4; nt++) {
                        int np = 8 * nt + 2 * tig;   // n within this 32-chunk
                        Cs[np * 132 + m]           = acc[mt][nt][0];
                        Cs[(np + 1) * 132 + m]     = acc[mt][nt][1];
                        Cs[np * 132 + m + 8]       = acc[mt][nt][2];
                        Cs[(np + 1) * 132 + m + 8] = acc[mt][nt][3];
                    }
                }
            }
            __syncthreads();
#pragma unroll
            for (int i = 0; i < 4; i++) {
                int idx = tid + 256 * i;          // 0..1023
                int row = idx >> 5;               // 0..31
                int m4 = (idx & 31) * 4;
                float4 c = *(float4*)&Cs[row * 132 + m4];
                long o = (long)(bn + p * 32 + row) * M + bm + m4;
                float4 r = *(const float4*)&resid[o];
                c.x += r.x; c.y += r.y; c.z += r.z; c.w += r.w;
                *(float4*)&Cmat[o] = c;
            }
            __syncthreads();
        }
    }
}

// ---------------------------------------------------------------------------
// Kernel 3: per-(window, head) RoPE + full 32x32 attention.
// ---------------------------------------------------------------------------
__global__ void __launch_bounds__(256) attn_kernel(float* __restrict__ att)
{
    const int w = blockIdx.x;
    const int h = blockIdx.y;
    const int t0 = w * WIN;
    const int tid = threadIdx.x;

    __shared__ float qs[32][65];
    __shared__ float ks[32][65];
    __shared__ float vs[32][65];
    __shared__ float ls[32][33];

    const float LOG1E4 = 9.210340371976184f;

    for (int e = tid; e < 32 * 64; e += 256) {
        int n = e >> 6;
        int d = e & 63;
        long row = (long)(t0 + n) * QKVN;
        float q = g_qkv[row + h * 64 + d];
        float k = g_qkv[row + 1024 + h * 64 + d];
        float v = g_qkv[row + 2048 + h * 64 + d];
        int j = d & 31;
        float inv = expf(-((float)j / 32.f) * LOG1E4);
        float ang = (float)n * inv;
        float sn, cs;
        sincosf(ang, &sn, &cs);
        float qr, kr;
        if (d < 32) {
            qr = -g_qkv[row + h * 64 + d + 32];
            kr = -g_qkv[row + 1024 + h * 64 + d + 32];
        } else {
            qr = g_qkv[row + h * 64 + d - 32];
            kr = g_qkv[row + 1024 + h * 64 + d - 32];
        }
        qs[n][d] = q * cs + qr * sn;
        ks[n][d] = k * cs + kr * sn;
        vs[n][d] = v;
    }
    __syncthreads();

    for (int e = tid; e < 32 * 32; e += 256) {
        int n = e >> 5;
        int m = e & 31;
        float a = 0.f;
#pragma unroll
        for (int d = 0; d < 64; d++) a = fmaf(qs[n][d], ks[m][d], a);
        ls[n][m] = a * 0.125f;
    }
    __syncthreads();

    const int warp = tid >> 5, lane = tid & 31;
    for (int r = warp; r < 32; r += 8) {
        float v = ls[r][lane];
        float mx = v;
#pragma unroll
        for (int o = 16; o; o >>= 1) mx = fmaxf(mx, __shfl_xor_sync(0xffffffffu, mx, o));
        float ev = __expf(v - mx);
        float sm = ev;
#pragma unroll
        for (int o = 16; o; o >>= 1) sm += __shfl_xor_sync(0xffffffffu, sm, o);
        ls[r][lane] = ev / sm;
    }
    __syncthreads();

    for (int e = tid; e < 32 * 64; e += 256) {
        int n = e >> 6;
        int d = e & 63;
        float a = 0.f;
#pragma unroll
        for (int m = 0; m < 32; m++) a = fmaf(ls[n][m], vs[m][d], a);
        att[(long)(t0 + n) * CDIM + h * 64 + d] = a;
    }
}

// ---------------------------------------------------------------------------
extern "C" void kernel_launch(void* const* d_in, const int* in_sizes, int n_in,
                              void* d_out, int out_size)
{
    (void)in_sizes; (void)n_in; (void)out_size;
    const float* x     = (const float*)d_in[0];
    const float* wqkv  = (const float*)d_in[1];
    const float* wout  = (const float*)d_in[2];
    const float* gamma = (const float*)d_in[3];
    const float* beta  = (const float*)d_in[4];
    float* out = (float*)d_out;

    float *qkv, *buf;
    cudaGetSymbolAddress((void**)&qkv, g_qkv);
    cudaGetSymbolAddress((void**)&buf, g_buf);

    // 1. LayerNorm -> buf (= normed, (T, C))
    ln_kernel<<<TDIM / WIN, 256>>>(x, gamma, beta, buf);

    // 2. QKV GEMM: (T, C) x (3C, C)^T -> (T, 3C)
    tgemm_kernel<false><<<dim3(TDIM / 128, QKVN / 128), 256>>>(
        buf, wqkv, qkv, nullptr, TDIM, QKVN, CDIM);

    // 3. RoPE + windowed attention -> buf (= att, (T, C))
    attn_kernel<<<dim3(TDIM / WIN, NHEADS), 256>>>(buf);

    // 4. Output GEMM + transposed residual epilogue -> d_out (C, T)
    tgemm_kernel<true><<<dim3(TDIM / 128, CDIM / 128), 256>>>(
        buf, wout, out, x, TDIM, CDIM, CDIM);
}

// round 11
// speedup vs baseline: 3.3276x; 1.0300x over previous
#include <cuda_runtime.h>
#include <cuda_fp16.h>
#include <cuda_bf16.h>
#include <math.h>
#include <stdint.h>

#define TDIM 16384
#define CDIM 1024
#define WIN 32
#define DHEAD 64
#define NHEADS 16
#define QKVN 3072

// Scratch (device globals; no allocation allowed).
__device__ float g_qkv[TDIM * QKVN];      // (T, 3C) 192 MB
__device__ float g_buf[TDIM * CDIM];      // (T, C)   64 MB  (normed, then att)
__device__ float g_rcos[WIN * DHEAD];     // RoPE cos table (32 x 64)
__device__ float g_rsin[WIN * DHEAD];     // RoPE sin table

// ---------------------------------------------------------------------------
// PTX helpers
// ---------------------------------------------------------------------------
__device__ __forceinline__ void mma_f16(float* c, const uint32_t* a, const uint32_t* b) {
    asm volatile(
        "mma.sync.aligned.m16n8k16.row.col.f32.f16.f16.f32 "
        "{%0,%1,%2,%3}, {%4,%5,%6,%7}, {%8,%9}, {%0,%1,%2,%3};"
        : "+f"(c[0]), "+f"(c[1]), "+f"(c[2]), "+f"(c[3])
        : "r"(a[0]), "r"(a[1]), "r"(a[2]), "r"(a[3]), "r"(b[0]), "r"(b[1]));
}

__device__ __forceinline__ uint32_t pack_h2(float x, float y) {
    __half2 h = __floats2half2_rn(x, y);
    return *(uint32_t*)&h;
}

// ---------------------------------------------------------------------------
// Kernel 0: RoPE table init (32 positions x 64 dims; 2048 threads total).
// ---------------------------------------------------------------------------
__global__ void rope_init_kernel() {
    int i = blockIdx.x * blockDim.x + threadIdx.x;   // 0..2047
    int n = i >> 6;
    int d = i & 63;
    const float LOG1E4 = 9.210340371976184f;
    float inv = expf(-((float)(d & 31) / 32.f) * LOG1E4);
    float ang = (float)n * inv;
    float sn, cs;
    sincosf(ang, &sn, &cs);
    g_rcos[i] = cs;
    g_rsin[i] = sn;
}

// ---------------------------------------------------------------------------
// Kernel 1: LayerNorm over channel dim. x is (C, T). Output (T, C).
// ---------------------------------------------------------------------------
__global__ void __launch_bounds__(256) ln_kernel(
    const float* __restrict__ x,
    const float* __restrict__ gamma,
    const float* __restrict__ beta,
    float* __restrict__ out)
{
    const int t0 = blockIdx.x * WIN;
    const int tx = threadIdx.x & 31;
    const int ty = threadIdx.x >> 5;

    __shared__ float rs[8][32];
    __shared__ float rs2[8][32];
    __shared__ float s_mu[32];
    __shared__ float s_rsig[32];
    __shared__ float tile[32][33];

    float s = 0.f, s2 = 0.f;
    const int t = t0 + tx;
    for (int c = ty; c < CDIM; c += 8) {
        float v = x[c * TDIM + t];
        s += v; s2 += v * v;
    }
    rs[ty][tx] = s; rs2[ty][tx] = s2;
    __syncthreads();
    if (ty == 0) {
        float a = 0.f, b = 0.f;
#pragma unroll
        for (int j = 0; j < 8; j++) { a += rs[j][tx]; b += rs2[j][tx]; }
        float mu = a * (1.0f / CDIM);
        float var = b * (1.0f / CDIM) - mu * mu;
        s_mu[tx] = mu;
        s_rsig[tx] = rsqrtf(var + 1e-5f);
    }
    __syncthreads();

    for (int c0 = 0; c0 < CDIM; c0 += 32) {
        for (int r = ty; r < 32; r += 8)
            tile[r][tx] = x[(c0 + r) * TDIM + t0 + tx];
        __syncthreads();
        float g = gamma[c0 + tx];
        float be = beta[c0 + tx];
        for (int tl = ty; tl < 32; tl += 8) {
            float v = tile[tx][tl];
            out[(t0 + tl) * CDIM + c0 + tx] = (v - s_mu[tl]) * s_rsig[tl] * g + be;
        }
        __syncthreads();
    }
}

// ---------------------------------------------------------------------------
// FP16 tensor-core GEMM (f32 accumulate):  C[m][n] = sum_k A[m][k] * B[n][k]
//   A: (M,K) row-major fp32, B: (N,K) row-major fp32; converted to fp16 at STS.
// 128x128 block tile, Ktile=16, 256 threads (8 warps, 2x4), warp tile 64x32,
// 4x4 m16n8k16 microtiles. Smem fp16 m-major [row][k], row stride 24 halves
// (12 words: fragment-load banks 12g+tig mod 32 = full permutation).
// DOUBLE-BUFFERED: one __syncthreads per ktile; ldg(next) overlaps mma(cur).
// TRANS_RESID: out[n*M+m] = acc + resid[n*M+m], staged 32 n-rows at a time.
// ---------------------------------------------------------------------------
#define KSH 24                    // halves per smem row (48 B)
#define TILEH (128 * KSH)         // 3072 halves per matrix tile

template <bool TRANS_RESID>
__global__ void __launch_bounds__(256) tgemm_kernel(
    const float* __restrict__ A,
    const float* __restrict__ B,
    float* __restrict__ Cmat,
    const float* __restrict__ resid,
    int M, int N, int K)
{
    __shared__ __align__(16) __half sh[2][2 * TILEH];   // 24576 B, static

    const int bm = blockIdx.x * 128;
    const int bn = blockIdx.y * 128;
    const int tid = threadIdx.x;
    const int warp = tid >> 5;
    const int lane = tid & 31;
    const int g = lane >> 2;       // 0..7
    const int tig = lane & 3;      // 0..3
    const int wm = (warp & 1) * 64;
    const int wn = (warp >> 1) * 32;

    const int lrow = tid >> 2;       // 0..63
    const int lk4  = (tid & 3) * 4;  // 0,4,8,12

    float acc[4][4][4];
#pragma unroll
    for (int i = 0; i < 4; i++)
#pragma unroll
        for (int j = 0; j < 4; j++)
#pragma unroll
            for (int r = 0; r < 4; r++) acc[i][j][r] = 0.f;

    float4 ra[2], rb[2];

    // Prologue: K-tile 0 -> registers -> fp16 -> smem buffer 0.
#pragma unroll
    for (int rr = 0; rr < 2; rr++) {
        ra[rr] = *(const float4*)&A[(long)(bm + lrow + rr * 64) * K + lk4];
        rb[rr] = *(const float4*)&B[(long)(bn + lrow + rr * 64) * K + lk4];
    }
#pragma unroll
    for (int rr = 0; rr < 2; rr++) {
        int m = lrow + rr * 64;
        *(uint2*)&sh[0][m * KSH + lk4] =
            make_uint2(pack_h2(ra[rr].x, ra[rr].y), pack_h2(ra[rr].z, ra[rr].w));
        *(uint2*)&sh[0][TILEH + m * KSH + lk4] =
            make_uint2(pack_h2(rb[rr].x, rb[rr].y), pack_h2(rb[rr].z, rb[rr].w));
    }
    __syncthreads();
    int cur = 0;

    const int NK = K >> 4;
    for (int kt = 0; kt < NK; kt++) {
        const bool more = (kt + 1 < NK);
        if (more) {
            const int k0 = (kt + 1) * 16;
#pragma unroll
            for (int rr = 0; rr < 2; rr++) {
                ra[rr] = *(const float4*)&A[(long)(bm + lrow + rr * 64) * K + k0 + lk4];
                rb[rr] = *(const float4*)&B[(long)(bn + lrow + rr * 64) * K + k0 + lk4];
            }
        }

        {
            const __half* As = sh[cur];
            const __half* Bs = sh[cur] + TILEH;
            const int kc = 2 * tig;           // half index within ktile
            uint32_t af[4][4], bf[4][2];
#pragma unroll
            for (int mt = 0; mt < 4; mt++) {
                int r0 = wm + 16 * mt + g;
                af[mt][0] = *(const uint32_t*)&As[r0 * KSH + kc];
                af[mt][1] = *(const uint32_t*)&As[(r0 + 8) * KSH + kc];
                af[mt][2] = *(const uint32_t*)&As[r0 * KSH + kc + 8];
                af[mt][3] = *(const uint32_t*)&As[(r0 + 8) * KSH + kc + 8];
            }
#pragma unroll
            for (int nt = 0; nt < 4; nt++) {
                int n0 = wn + 8 * nt + g;
                bf[nt][0] = *(const uint32_t*)&Bs[n0 * KSH + kc];
                bf[nt][1] = *(const uint32_t*)&Bs[n0 * KSH + kc + 8];
            }
#pragma unroll
            for (int mt = 0; mt < 4; mt++)
#pragma unroll
                for (int nt = 0; nt < 4; nt++)
                    mma_f16(acc[mt][nt], af[mt], bf[nt]);
        }

        if (more) {
            const int nxt = cur ^ 1;
#pragma unroll
            for (int rr = 0; rr < 2; rr++) {
                int m = lrow + rr * 64;
                *(uint2*)&sh[nxt][m * KSH + lk4] =
                    make_uint2(pack_h2(ra[rr].x, ra[rr].y), pack_h2(ra[rr].z, ra[rr].w));
                *(uint2*)&sh[nxt][TILEH + m * KSH + lk4] =
                    make_uint2(pack_h2(rb[rr].x, rb[rr].y), pack_h2(rb[rr].z, rb[rr].w));
            }
            __syncthreads();
            cur = nxt;
        }
    }

    if (!TRANS_RESID) {
#pragma unroll
        for (int mt = 0; mt < 4; mt++) {
            int m = bm + wm + 16 * mt + g;
#pragma unroll
            for (int nt = 0; nt < 4; nt++) {
                int n = bn + wn + 8 * nt + 2 * tig;
                *(float2*)&Cmat[(long)m * N + n] =
                    make_float2(acc[mt][nt][0], acc[mt][nt][1]);
                *(float2*)&Cmat[(long)(m + 8) * N + n] =
                    make_float2(acc[mt][nt][2], acc[mt][nt][3]);
            }
        }
    } else {
        // out is (N, M). Stage 32 n-rows (one warp-pair's n-range) per pass in
        // smem transposed as Cs[n'][m], stride 132, then coalesced float4 out.
        float* Cs = (float*)sh;    // 32*132*4 = 16896 B <= 24576
        __syncthreads();           // all warps done reading mma smem
#pragma unroll
        for (int p = 0; p < 4; p++) {
            if ((warp >> 1) == p) {
#pragma unroll
                for (int mt = 0; mt < 4; mt++) {
                    int m = wm + 16 * mt + g;
#pragma unroll
                    for (int nt = 0; nt < 4; nt++) {
                        int np = 8 * nt + 2 * tig;   // n within this 32-chunk
                        Cs[np * 132 + m]           = acc[mt][nt][0];
                        Cs[(np + 1) * 132 + m]     = acc[mt][nt][1];
                        Cs[np * 132 + m + 8]       = acc[mt][nt][2];
                        Cs[(np + 1) * 132 + m + 8] = acc[mt][nt][3];
                    }
                }
            }
            __syncthreads();
#pragma unroll
            for (int i = 0; i < 4; i++) {
                int idx = tid + 256 * i;          // 0..1023
                int row = idx >> 5;               // 0..31
                int m4 = (idx & 31) * 4;
                float4 c = *(float4*)&Cs[row * 132 + m4];
                long o = (long)(bn + p * 32 + row) * M + bm + m4;
                float4 r = *(const float4*)&resid[o];
                c.x += r.x; c.y += r.y; c.z += r.z; c.w += r.w;
                *(float4*)&Cmat[o] = c;
            }
            __syncthreads();
        }
    }
}

// ---------------------------------------------------------------------------
// Kernel 3: per-(window, head) RoPE + full 32x32 attention.
// RoPE angles come from the precomputed g_rcos/g_rsin tables.
// ---------------------------------------------------------------------------
__global__ void __launch_bounds__(256) attn_kernel(float* __restrict__ att)
{
    const int w = blockIdx.x;
    const int h = blockIdx.y;
    const int t0 = w * WIN;
    const int tid = threadIdx.x;

    __shared__ float qs[32][65];
    __shared__ float ks[32][65];
    __shared__ float vs[32][65];
    __shared__ float ls[32][33];

    for (int e = tid; e < 32 * 64; e += 256) {
        int n = e >> 6;
        int d = e & 63;
        long row = (long)(t0 + n) * QKVN;
        float q = g_qkv[row + h * 64 + d];
        float k = g_qkv[row + 1024 + h * 64 + d];
        float v = g_qkv[row + 2048 + h * 64 + d];
        float cs = g_rcos[e & 2047];
        float sn = g_rsin[e & 2047];
        float qr, kr;
        if (d < 32) {
            qr = -g_qkv[row + h * 64 + d + 32];
            kr = -g_qkv[row + 1024 + h * 64 + d + 32];
        } else {
            qr = g_qkv[row + h * 64 + d - 32];
            kr = g_qkv[row + 1024 + h * 64 + d - 32];
        }
        qs[n][d] = q * cs + qr * sn;
        ks[n][d] = k * cs + kr * sn;
        vs[n][d] = v;
    }
    __syncthreads();

    for (int e = tid; e < 32 * 32; e += 256) {
        int n = e >> 5;
        int m = e & 31;
        float a = 0.f;
#pragma unroll
        for (int d = 0; d < 64; d++) a = fmaf(qs[n][d], ks[m][d], a);
        ls[n][m] = a * 0.125f;
    }
    __syncthreads();

    const int warp = tid >> 5, lane = tid & 31;
    for (int r = warp; r < 32; r += 8) {
        float v = ls[r][lane];
        float mx = v;
#pragma unroll
        for (int o = 16; o; o >>= 1) mx = fmaxf(mx, __shfl_xor_sync(0xffffffffu, mx, o));
        float ev = __expf(v - mx);
        float sm = ev;
#pragma unroll
        for (int o = 16; o; o >>= 1) sm += __shfl_xor_sync(0xffffffffu, sm, o);
        ls[r][lane] = ev / sm;
    }
    __syncthreads();

    for (int e = tid; e < 32 * 64; e += 256) {
        int n = e >> 6;
        int d = e & 63;
        float a = 0.f;
#pragma unroll
        for (int m = 0; m < 32; m++) a = fmaf(ls[n][m], vs[m][d], a);
        att[(long)(t0 + n) * CDIM + h * 64 + d] = a;
    }
}

// ---------------------------------------------------------------------------
extern "C" void kernel_launch(void* const* d_in, const int* in_sizes, int n_in,
                              void* d_out, int out_size)
{
    (void)in_sizes; (void)n_in; (void)out_size;
    const float* x     = (const float*)d_in[0];
    const float* wqkv  = (const float*)d_in[1];
    const float* wout  = (const float*)d_in[2];
    const float* gamma = (const float*)d_in[3];
    const float* beta  = (const float*)d_in[4];
    float* out = (float*)d_out;

    float *qkv, *buf;
    cudaGetSymbolAddress((void**)&qkv, g_qkv);
    cudaGetSymbolAddress((void**)&buf, g_buf);

    // 0. RoPE table (2048 entries; idempotent, deterministic)
    rope_init_kernel<<<8, 256>>>();

    // 1. LayerNorm -> buf (= normed, (T, C))
    ln_kernel<<<TDIM / WIN, 256>>>(x, gamma, beta, buf);

    // 2. QKV GEMM: (T, C) x (3C, C)^T -> (T, 3C)
    tgemm_kernel<false><<<dim3(TDIM / 128, QKVN / 128), 256>>>(
        buf, wqkv, qkv, nullptr, TDIM, QKVN, CDIM);

    // 3. RoPE + windowed attention -> buf (= att, (T, C))
    attn_kernel<<<dim3(TDIM / WIN, NHEADS), 256>>>(buf);

    // 4. Output GEMM + transposed residual epilogue -> d_out (C, T)
    tgemm_kernel<true><<<dim3(TDIM / 128, CDIM / 128), 256>>>(
        buf, wout, out, x, TDIM, CDIM, CDIM);
}

// round 13
// speedup vs baseline: 3.8264x; 1.1499x over previous
#include <cuda_runtime.h>
#include <cuda_fp16.h>
#include <cuda_bf16.h>
#include <math.h>
#include <stdint.h>

#define TDIM 16384
#define CDIM 1024
#define WIN 32
#define DHEAD 64
#define NHEADS 16
#define QKVN 3072

// Scratch (device globals; no allocation allowed).
__device__ float g_qkv[TDIM * QKVN];      // (T, 3C) 192 MB
__device__ float g_buf[TDIM * CDIM];      // (T, C)   64 MB  (normed, then att)
__device__ float g_rcos[WIN * DHEAD];     // RoPE cos table (32 x 64)
__device__ float g_rsin[WIN * DHEAD];     // RoPE sin table

// ---------------------------------------------------------------------------
// PTX helpers
// ---------------------------------------------------------------------------
__device__ __forceinline__ void mma_f16(float* c, const uint32_t* a, const uint32_t* b) {
    asm volatile(
        "mma.sync.aligned.m16n8k16.row.col.f32.f16.f16.f32 "
        "{%0,%1,%2,%3}, {%4,%5,%6,%7}, {%8,%9}, {%0,%1,%2,%3};"
        : "+f"(c[0]), "+f"(c[1]), "+f"(c[2]), "+f"(c[3])
        : "r"(a[0]), "r"(a[1]), "r"(a[2]), "r"(a[3]), "r"(b[0]), "r"(b[1]));
}

__device__ __forceinline__ void ldsm_x4(uint32_t& r0, uint32_t& r1,
                                        uint32_t& r2, uint32_t& r3, uint32_t addr) {
    asm volatile("ldmatrix.sync.aligned.m8n8.x4.shared.b16 {%0,%1,%2,%3}, [%4];"
        : "=r"(r0), "=r"(r1), "=r"(r2), "=r"(r3) : "r"(addr));
}

__device__ __forceinline__ uint32_t pack_h2(float x, float y) {
    __half2 h = __floats2half2_rn(x, y);
    return *(uint32_t*)&h;
}

// ---------------------------------------------------------------------------
// Kernel 0: RoPE table init (32 positions x 64 dims; 2048 threads total).
// ---------------------------------------------------------------------------
__global__ void rope_init_kernel() {
    int i = blockIdx.x * blockDim.x + threadIdx.x;   // 0..2047
    int n = i >> 6;
    int d = i & 63;
    const float LOG1E4 = 9.210340371976184f;
    float inv = expf(-((float)(d & 31) / 32.f) * LOG1E4);
    float ang = (float)n * inv;
    float sn, cs;
    sincosf(ang, &sn, &cs);
    g_rcos[i] = cs;
    g_rsin[i] = sn;
}

// ---------------------------------------------------------------------------
// Kernel 1: LayerNorm over channel dim. x is (C, T). Output (T, C).
// ---------------------------------------------------------------------------
__global__ void __launch_bounds__(256) ln_kernel(
    const float* __restrict__ x,
    const float* __restrict__ gamma,
    const float* __restrict__ beta,
    float* __restrict__ out)
{
    const int t0 = blockIdx.x * WIN;
    const int tx = threadIdx.x & 31;
    const int ty = threadIdx.x >> 5;

    __shared__ float rs[8][32];
    __shared__ float rs2[8][32];
    __shared__ float s_mu[32];
    __shared__ float s_rsig[32];
    __shared__ float tile[32][33];

    float s = 0.f, s2 = 0.f;
    const int t = t0 + tx;
    for (int c = ty; c < CDIM; c += 8) {
        float v = x[c * TDIM + t];
        s += v; s2 += v * v;
    }
    rs[ty][tx] = s; rs2[ty][tx] = s2;
    __syncthreads();
    if (ty == 0) {
        float a = 0.f, b = 0.f;
#pragma unroll
        for (int j = 0; j < 8; j++) { a += rs[j][tx]; b += rs2[j][tx]; }
        float mu = a * (1.0f / CDIM);
        float var = b * (1.0f / CDIM) - mu * mu;
        s_mu[tx] = mu;
        s_rsig[tx] = rsqrtf(var + 1e-5f);
    }
    __syncthreads();

    for (int c0 = 0; c0 < CDIM; c0 += 32) {
        for (int r = ty; r < 32; r += 8)
            tile[r][tx] = x[(c0 + r) * TDIM + t0 + tx];
        __syncthreads();
        float g = gamma[c0 + tx];
        float be = beta[c0 + tx];
        for (int tl = ty; tl < 32; tl += 8) {
            float v = tile[tx][tl];
            out[(t0 + tl) * CDIM + c0 + tx] = (v - s_mu[tl]) * s_rsig[tl] * g + be;
        }
        __syncthreads();
    }
}

// ---------------------------------------------------------------------------
// FP16 tensor-core GEMM (f32 accumulate):  C[m][n] = sum_k A[m][k] * B[n][k]
// 128x128 block tile, Ktile=16, 256 threads (8 warps, 2x4), warp tile 64x32,
// 4x4 m16n8k16 microtiles. Fragments loaded via ldmatrix.x4 (6 LDSM per
// warp-ktile instead of 24 scalar LDS). Smem fp16 [row][k], stride 24 halves
// (LDSM-conflict-free: 12r mod 32 is a permutation). Double-buffered.
// TRANS_RESID: out[n*M+m] = acc + resid[n*M+m], staged 32 n-rows at a time.
// ---------------------------------------------------------------------------
#define KSH 24                    // halves per smem row (48 B)
#define TILEH (128 * KSH)         // 3072 halves per matrix tile

template <bool TRANS_RESID>
__global__ void __launch_bounds__(256) tgemm_kernel(
    const float* __restrict__ A,
    const float* __restrict__ B,
    float* __restrict__ Cmat,
    const float* __restrict__ resid,
    int M, int N, int K)
{
    __shared__ __align__(16) __half sh[2][2 * TILEH];   // 24576 B, static

    const int bm = blockIdx.x * 128;
    const int bn = blockIdx.y * 128;
    const int tid = threadIdx.x;
    const int warp = tid >> 5;
    const int lane = tid & 31;
    const int g = lane >> 2;       // 0..7
    const int tig = lane & 3;      // 0..3
    const int wm = (warp & 1) * 64;
    const int wn = (warp >> 1) * 32;

    const int lrow = tid >> 2;       // 0..63
    const int lk4  = (tid & 3) * 4;  // 0,4,8,12

    // ldmatrix per-lane address offsets (in halves, relative to tile base)
    const int l8 = lane & 7;
    const int sel = lane >> 3;       // 0..3
    int aoff[4], boff[2];
#pragma unroll
    for (int mt = 0; mt < 4; mt++)
        aoff[mt] = (wm + 16 * mt + l8 + (sel & 1) * 8) * KSH + (sel >> 1) * 8;
#pragma unroll
    for (int j = 0; j < 2; j++)
        boff[j] = (wn + 16 * j + (sel >> 1) * 8 + l8) * KSH + (sel & 1) * 8;

    float acc[4][4][4];
#pragma unroll
    for (int i = 0; i < 4; i++)
#pragma unroll
        for (int j = 0; j < 4; j++)
#pragma unroll
            for (int r = 0; r < 4; r++) acc[i][j][r] = 0.f;

    float4 ra[2], rb[2];

    // Prologue: K-tile 0 -> registers -> fp16 -> smem buffer 0.
#pragma unroll
    for (int rr = 0; rr < 2; rr++) {
        ra[rr] = *(const float4*)&A[(long)(bm + lrow + rr * 64) * K + lk4];
        rb[rr] = *(const float4*)&B[(long)(bn + lrow + rr * 64) * K + lk4];
    }
#pragma unroll
    for (int rr = 0; rr < 2; rr++) {
        int m = lrow + rr * 64;
        *(uint2*)&sh[0][m * KSH + lk4] =
            make_uint2(pack_h2(ra[rr].x, ra[rr].y), pack_h2(ra[rr].z, ra[rr].w));
        *(uint2*)&sh[0][TILEH + m * KSH + lk4] =
            make_uint2(pack_h2(rb[rr].x, rb[rr].y), pack_h2(rb[rr].z, rb[rr].w));
    }
    __syncthreads();
    int cur = 0;

    const int NK = K >> 4;
    for (int kt = 0; kt < NK; kt++) {
        const bool more = (kt + 1 < NK);
        if (more) {
            const int k0 = (kt + 1) * 16;
#pragma unroll
            for (int rr = 0; rr < 2; rr++) {
                ra[rr] = *(const float4*)&A[(long)(bm + lrow + rr * 64) * K + k0 + lk4];
                rb[rr] = *(const float4*)&B[(long)(bn + lrow + rr * 64) * K + k0 + lk4];
            }
        }

        {
            const uint32_t a_base = (uint32_t)__cvta_generic_to_shared(sh[cur]);
            const uint32_t b_base = a_base + TILEH * 2;
            uint32_t af[4][4], bf[4][2];
#pragma unroll
            for (int mt = 0; mt < 4; mt++)
                ldsm_x4(af[mt][0], af[mt][1], af[mt][2], af[mt][3],
                        a_base + 2 * aoff[mt]);
#pragma unroll
            for (int j = 0; j < 2; j++)
                ldsm_x4(bf[2*j][0], bf[2*j][1], bf[2*j+1][0], bf[2*j+1][1],
                        b_base + 2 * boff[j]);
#pragma unroll
            for (int mt = 0; mt < 4; mt++)
#pragma unroll
                for (int nt = 0; nt < 4; nt++)
                    mma_f16(acc[mt][nt], af[mt], bf[nt]);
        }

        if (more) {
            const int nxt = cur ^ 1;
#pragma unroll
            for (int rr = 0; rr < 2; rr++) {
                int m = lrow + rr * 64;
                *(uint2*)&sh[nxt][m * KSH + lk4] =
                    make_uint2(pack_h2(ra[rr].x, ra[rr].y), pack_h2(ra[rr].z, ra[rr].w));
                *(uint2*)&sh[nxt][TILEH + m * KSH + lk4] =
                    make_uint2(pack_h2(rb[rr].x, rb[rr].y), pack_h2(rb[rr].z, rb[rr].w));
            }
            __syncthreads();
            cur = nxt;
        }
    }

    if (!TRANS_RESID) {
#pragma unroll
        for (int mt = 0; mt < 4; mt++) {
            int m = bm + wm + 16 * mt + g;
#pragma unroll
            for (int nt = 0; nt < 4; nt++) {
                int n = bn + wn + 8 * nt + 2 * tig;
                *(float2*)&Cmat[(long)m * N + n] =
                    make_float2(acc[mt][nt][0], acc[mt][nt][1]);
                *(float2*)&Cmat[(long)(m + 8) * N + n] =
                    make_float2(acc[mt][nt][2], acc[mt][nt][3]);
            }
        }
    } else {
        // out is (N, M). Stage 32 n-rows (one warp-pair's n-range) per pass in
        // smem transposed as Cs[n'][m], stride 132, then coalesced float4 out.
        float* Cs = (float*)sh;    // 32*132*4 = 16896 B <= 24576
        __syncthreads();           // all warps done reading mma smem
#pragma unroll
        for (int p = 0; p < 4; p++) {
            if ((warp >> 1) == p) {
#pragma unroll
                for (int mt = 0; mt < 4; mt++) {
                    int m = wm + 16 * mt + g;
#pragma unroll
                    for (int nt = 0; nt < 4; nt++) {
                        int np = 8 * nt + 2 * tig;   // n within this 32-chunk
                        Cs[np * 132 + m]           = acc[mt][nt][0];
                        Cs[(np + 1) * 132 + m]     = acc[mt][nt][1];
                        Cs[np * 132 + m + 8]       = acc[mt][nt][2];
                        Cs[(np + 1) * 132 + m + 8] = acc[mt][nt][3];
                    }
                }
            }
            __syncthreads();
#pragma unroll
            for (int i = 0; i < 4; i++) {
                int idx = tid + 256 * i;          // 0..1023
                int row = idx >> 5;               // 0..31
                int m4 = (idx & 31) * 4;
                float4 c = *(float4*)&Cs[row * 132 + m4];
                long o = (long)(bn + p * 32 + row) * M + bm + m4;
                float4 r = *(const float4*)&resid[o];
                c.x += r.x; c.y += r.y; c.z += r.z; c.w += r.w;
                *(float4*)&Cmat[o] = c;
            }
            __syncthreads();
        }
    }
}

// ---------------------------------------------------------------------------
// Kernel 3: per-(window, head) RoPE + full 32x32 attention.
// Register-tiled fp32: QK as 2x2 tiles with float2 LDS; PV as 2x4 tiles
// with float4 V loads. RoPE angles from precomputed tables.
// ---------------------------------------------------------------------------
__global__ void __launch_bounds__(256) attn_kernel(float* __restrict__ att)
{
    const int w = blockIdx.x;
    const int h = blockIdx.y;
    const int t0 = w * WIN;
    const int tid = threadIdx.x;

    __shared__ float qs[32][66];   // stride 66 (even -> float2 aligned)
    __shared__ float ks[32][66];
    __shared__ float vs[32][68];   // stride 68 (mult of 4 -> float4 aligned)
    __shared__ float ls[32][33];

    for (int e = tid; e < 32 * 64; e += 256) {
        int n = e >> 6;
        int d = e & 63;
        long row = (long)(t0 + n) * QKVN;
        float q = g_qkv[row + h * 64 + d];
        float k = g_qkv[row + 1024 + h * 64 + d];
        float v = g_qkv[row + 2048 + h * 64 + d];
        float cs = g_rcos[e];
        float sn = g_rsin[e];
        float qr, kr;
        if (d < 32) {
            qr = -g_qkv[row + h * 64 + d + 32];
            kr = -g_qkv[row + 1024 + h * 64 + d + 32];
        } else {
            qr = g_qkv[row + h * 64 + d - 32];
            kr = g_qkv[row + 1024 + h * 64 + d - 32];
        }
        qs[n][d] = q * cs + qr * sn;
        ks[n][d] = k * cs + kr * sn;
        vs[n][d] = v;
    }
    __syncthreads();

    // QK^T: each thread computes a 2x2 logit tile with float2 LDS.
    {
        const int n0 = (tid >> 4) * 2;
        const int m0 = (tid & 15) * 2;
        float a00 = 0.f, a01 = 0.f, a10 = 0.f, a11 = 0.f;
#pragma unroll
        for (int d = 0; d < 64; d += 2) {
            float2 q0 = *(const float2*)&qs[n0][d];
            float2 q1 = *(const float2*)&qs[n0 + 1][d];
            float2 k0 = *(const float2*)&ks[m0][d];
            float2 k1 = *(const float2*)&ks[m0 + 1][d];
            a00 = fmaf(q0.x, k0.x, a00); a00 = fmaf(q0.y, k0.y, a00);
            a01 = fmaf(q0.x, k1.x, a01); a01 = fmaf(q0.y, k1.y, a01);
            a10 = fmaf(q1.x, k0.x, a10); a10 = fmaf(q1.y, k0.y, a10);
            a11 = fmaf(q1.x, k1.x, a11); a11 = fmaf(q1.y, k1.y, a11);
        }
        ls[n0][m0]         = a00 * 0.125f;
        ls[n0][m0 + 1]     = a01 * 0.125f;
        ls[n0 + 1][m0]     = a10 * 0.125f;
        ls[n0 + 1][m0 + 1] = a11 * 0.125f;
    }
    __syncthreads();

    const int warp = tid >> 5, lane = tid & 31;
    for (int r = warp; r < 32; r += 8) {
        float v = ls[r][lane];
        float mx = v;
#pragma unroll
        for (int o = 16; o; o >>= 1) mx = fmaxf(mx, __shfl_xor_sync(0xffffffffu, mx, o));
        float ev = __expf(v - mx);
        float sm = ev;
#pragma unroll
        for (int o = 16; o; o >>= 1) sm += __shfl_xor_sync(0xffffffffu, sm, o);
        ls[r][lane] = ev / sm;
    }
    __syncthreads();

    // PV: each thread computes 2 rows x 4 cols with float4 V loads.
    {
        const int n0 = (tid >> 4) * 2;
        const int d0 = (tid & 15) * 4;
        float4 o0 = make_float4(0.f, 0.f, 0.f, 0.f);
        float4 o1 = make_float4(0.f, 0.f, 0.f, 0.f);
#pragma unroll
        for (int m = 0; m < 32; m++) {
            float p0 = ls[n0][m];
            float p1 = ls[n0 + 1][m];
            float4 v4 = *(const float4*)&vs[m][d0];
            o0.x = fmaf(p0, v4.x, o0.x); o0.y = fmaf(p0, v4.y, o0.y);
            o0.z = fmaf(p0, v4.z, o0.z); o0.w = fmaf(p0, v4.w, o0.w);
            o1.x = fmaf(p1, v4.x, o1.x); o1.y = fmaf(p1, v4.y, o1.y);
            o1.z = fmaf(p1, v4.z, o1.z); o1.w = fmaf(p1, v4.w, o1.w);
        }
        *(float4*)&att[(long)(t0 + n0) * CDIM + h * 64 + d0] = o0;
        *(float4*)&att[(long)(t0 + n0 + 1) * CDIM + h * 64 + d0] = o1;
    }
}

// ---------------------------------------------------------------------------
extern "C" void kernel_launch(void* const* d_in, const int* in_sizes, int n_in,
                              void* d_out, int out_size)
{
    (void)in_sizes; (void)n_in; (void)out_size;
    const float* x     = (const float*)d_in[0];
    const float* wqkv  = (const float*)d_in[1];
    const float* wout  = (const float*)d_in[2];
    const float* gamma = (const float*)d_in[3];
    const float* beta  = (const float*)d_in[4];
    float* out = (float*)d_out;

    float *qkv, *buf;
    cudaGetSymbolAddress((void**)&qkv, g_qkv);
    cudaGetSymbolAddress((void**)&buf, g_buf);

    // 0. RoPE table (2048 entries; idempotent, deterministic)
    rope_init_kernel<<<8, 256>>>();

    // 1. LayerNorm -> buf (= normed, (T, C))
    ln_kernel<<<TDIM / WIN, 256>>>(x, gamma, beta, buf);

    // 2. QKV GEMM: (T, C) x (3C, C)^T -> (T, 3C)
    tgemm_kernel<false><<<dim3(TDIM / 128, QKVN / 128), 256>>>(
        buf, wqkv, qkv, nullptr, TDIM, QKVN, CDIM);

    // 3. RoPE + windowed attention -> buf (= att, (T, C))
    attn_kernel<<<dim3(TDIM / WIN, NHEADS), 256>>>(buf);

    // 4. Output GEMM + transposed residual epilogue -> d_out (C, T)
    tgemm_kernel<true><<<dim3(TDIM / 128, CDIM / 128), 256>>>(
        buf, wout, out, x, TDIM, CDIM, CDIM);
}

// round 15
// speedup vs baseline: 4.2561x; 1.1123x over previous
#include <cuda_runtime.h>
#include <cuda_fp16.h>
#include <cuda_bf16.h>
#include <math.h>
#include <stdint.h>

#define TDIM 16384
#define CDIM 1024
#define WIN 32
#define DHEAD 64
#define NHEADS 16
#define QKVN 3072

// Scratch (device globals; no allocation allowed).
__device__ float  g_qkv[TDIM * QKVN];        // (T, 3C) fp32, 192 MB
__device__ __half g_nh[TDIM * CDIM];         // normed (T, C) fp16, 32 MB
__device__ __half g_att_h[TDIM * CDIM];      // attention out (T, C) fp16, 32 MB
__device__ __half g_wqkv_h[QKVN * CDIM];     // w_qkv fp16, 6 MB
__device__ __half g_wout_h[CDIM * CDIM];     // w_out fp16, 2 MB
__device__ float  g_rcos[WIN * DHEAD];       // RoPE cos table (32 x 64)
__device__ float  g_rsin[WIN * DHEAD];       // RoPE sin table

// ---------------------------------------------------------------------------
// PTX helpers
// ---------------------------------------------------------------------------
__device__ __forceinline__ void mma_f16(float* c, const uint32_t* a, const uint32_t* b) {
    asm volatile(
        "mma.sync.aligned.m16n8k16.row.col.f32.f16.f16.f32 "
        "{%0,%1,%2,%3}, {%4,%5,%6,%7}, {%8,%9}, {%0,%1,%2,%3};"
        : "+f"(c[0]), "+f"(c[1]), "+f"(c[2]), "+f"(c[3])
        : "r"(a[0]), "r"(a[1]), "r"(a[2]), "r"(a[3]), "r"(b[0]), "r"(b[1]));
}

__device__ __forceinline__ void ldsm_x4(uint32_t& r0, uint32_t& r1,
                                        uint32_t& r2, uint32_t& r3, uint32_t addr) {
    asm volatile("ldmatrix.sync.aligned.m8n8.x4.shared.b16 {%0,%1,%2,%3}, [%4];"
        : "=r"(r0), "=r"(r1), "=r"(r2), "=r"(r3) : "r"(addr));
}

__device__ __forceinline__ uint32_t pack_h2(float x, float y) {
    __half2 h = __floats2half2_rn(x, y);
    return *(uint32_t*)&h;
}

// ---------------------------------------------------------------------------
// Kernel 0a: RoPE table init (32 positions x 64 dims).
// ---------------------------------------------------------------------------
__global__ void rope_init_kernel() {
    int i = blockIdx.x * blockDim.x + threadIdx.x;   // 0..2047
    int n = i >> 6;
    int d = i & 63;
    const float LOG1E4 = 9.210340371976184f;
    float inv = expf(-((float)(d & 31) / 32.f) * LOG1E4);
    float ang = (float)n * inv;
    float sn, cs;
    sincosf(ang, &sn, &cs);
    g_rcos[i] = cs;
    g_rsin[i] = sn;
}

// ---------------------------------------------------------------------------
// Kernel 0b: weight fp32 -> fp16 conversion (one shot per launch, ~5us).
// ---------------------------------------------------------------------------
__global__ void __launch_bounds__(256) w16_kernel(
    const float* __restrict__ wqkv, const float* __restrict__ wout)
{
    const int NQ = QKVN * CDIM;
    const int NO = CDIM * CDIM;
    for (int i = blockIdx.x * blockDim.x + threadIdx.x; i < NQ;
         i += gridDim.x * blockDim.x)
        g_wqkv_h[i] = __float2half_rn(wqkv[i]);
    for (int i = blockIdx.x * blockDim.x + threadIdx.x; i < NO;
         i += gridDim.x * blockDim.x)
        g_wout_h[i] = __float2half_rn(wout[i]);
}

// ---------------------------------------------------------------------------
// Kernel 1: LayerNorm over channel dim. x is (C, T). Output (T, C) fp16.
// ---------------------------------------------------------------------------
__global__ void __launch_bounds__(256) ln_kernel(
    const float* __restrict__ x,
    const float* __restrict__ gamma,
    const float* __restrict__ beta,
    __half* __restrict__ out)
{
    const int t0 = blockIdx.x * WIN;
    const int tx = threadIdx.x & 31;
    const int ty = threadIdx.x >> 5;

    __shared__ float rs[8][32];
    __shared__ float rs2[8][32];
    __shared__ float s_mu[32];
    __shared__ float s_rsig[32];
    __shared__ float tile[32][33];

    float s = 0.f, s2 = 0.f;
    const int t = t0 + tx;
    for (int c = ty; c < CDIM; c += 8) {
        float v = x[c * TDIM + t];
        s += v; s2 += v * v;
    }
    rs[ty][tx] = s; rs2[ty][tx] = s2;
    __syncthreads();
    if (ty == 0) {
        float a = 0.f, b = 0.f;
#pragma unroll
        for (int j = 0; j < 8; j++) { a += rs[j][tx]; b += rs2[j][tx]; }
        float mu = a * (1.0f / CDIM);
        float var = b * (1.0f / CDIM) - mu * mu;
        s_mu[tx] = mu;
        s_rsig[tx] = rsqrtf(var + 1e-5f);
    }
    __syncthreads();

    for (int c0 = 0; c0 < CDIM; c0 += 32) {
        for (int r = ty; r < 32; r += 8)
            tile[r][tx] = x[(c0 + r) * TDIM + t0 + tx];
        __syncthreads();
        float g = gamma[c0 + tx];
        float be = beta[c0 + tx];
        for (int tl = ty; tl < 32; tl += 8) {
            float v = tile[tx][tl];
            out[(t0 + tl) * CDIM + c0 + tx] =
                __float2half_rn((v - s_mu[tl]) * s_rsig[tl] * g + be);
        }
        __syncthreads();
    }
}

// ---------------------------------------------------------------------------
// FP16 tensor-core GEMM (f32 accumulate):  C[m][n] = sum_k A[m][k] * B[n][k]
//   A: (M,K) fp16 row-major, B: (N,K) fp16 row-major (pre-converted).
// 128x128 block tile, Ktile=16, 256 threads (8 warps, 2x4), warp tile 64x32,
// 4x4 m16n8k16 microtiles via ldmatrix.x4. Smem fp16 [row][k] stride 24
// halves (LDSM conflict-free). Double-buffered; 1 uint4 LDG + 1 uint4 STS
// per matrix per thread per ktile.
// TRANS_RESID: out[n*M+m] = acc + resid[n*M+m] (fp32), staged 32 rows/pass.
// ---------------------------------------------------------------------------
#define KSH 24                    // halves per smem row (48 B)
#define TILEH (128 * KSH)         // 3072 halves per matrix tile

template <bool TRANS_RESID>
__global__ void __launch_bounds__(256) tgemm_kernel(
    const __half* __restrict__ A,
    const __half* __restrict__ B,
    float* __restrict__ Cmat,
    const float* __restrict__ resid,
    int M, int N, int K)
{
    __shared__ __align__(16) __half sh[2][2 * TILEH];   // 24576 B, static

    const int bm = blockIdx.x * 128;
    const int bn = blockIdx.y * 128;
    const int tid = threadIdx.x;
    const int warp = tid >> 5;
    const int lane = tid & 31;
    const int g = lane >> 2;       // 0..7
    const int tig = lane & 3;      // 0..3
    const int wm = (warp & 1) * 64;
    const int wn = (warp >> 1) * 32;

    const int lrow2 = tid >> 1;       // 0..127
    const int lseg  = (tid & 1) * 8;  // 0 or 8 (halves)

    // ldmatrix per-lane address offsets (in halves, relative to tile base)
    const int l8 = lane & 7;
    const int sel = lane >> 3;       // 0..3
    int aoff[4], boff[2];
#pragma unroll
    for (int mt = 0; mt < 4; mt++)
        aoff[mt] = (wm + 16 * mt + l8 + (sel & 1) * 8) * KSH + (sel >> 1) * 8;
#pragma unroll
    for (int j = 0; j < 2; j++)
        boff[j] = (wn + 16 * j + (sel >> 1) * 8 + l8) * KSH + (sel & 1) * 8;

    float acc[4][4][4];
#pragma unroll
    for (int i = 0; i < 4; i++)
#pragma unroll
        for (int j = 0; j < 4; j++)
#pragma unroll
            for (int r = 0; r < 4; r++) acc[i][j][r] = 0.f;

    uint4 ra, rb;

    // Prologue: K-tile 0 -> registers -> smem buffer 0.
    ra = *(const uint4*)&A[(long)(bm + lrow2) * K + lseg];
    rb = *(const uint4*)&B[(long)(bn + lrow2) * K + lseg];
    *(uint4*)&sh[0][lrow2 * KSH + lseg] = ra;
    *(uint4*)&sh[0][TILEH + lrow2 * KSH + lseg] = rb;
    __syncthreads();
    int cur = 0;

    const int NK = K >> 4;
    for (int kt = 0; kt < NK; kt++) {
        const bool more = (kt + 1 < NK);
        if (more) {
            const int k0 = (kt + 1) * 16;
            ra = *(const uint4*)&A[(long)(bm + lrow2) * K + k0 + lseg];
            rb = *(const uint4*)&B[(long)(bn + lrow2) * K + k0 + lseg];
        }

        {
            const uint32_t a_base = (uint32_t)__cvta_generic_to_shared(sh[cur]);
            const uint32_t b_base = a_base + TILEH * 2;
            uint32_t af[4][4], bf[4][2];
#pragma unroll
            for (int mt = 0; mt < 4; mt++)
                ldsm_x4(af[mt][0], af[mt][1], af[mt][2], af[mt][3],
                        a_base + 2 * aoff[mt]);
#pragma unroll
            for (int j = 0; j < 2; j++)
                ldsm_x4(bf[2*j][0], bf[2*j][1], bf[2*j+1][0], bf[2*j+1][1],
                        b_base + 2 * boff[j]);
#pragma unroll
            for (int mt = 0; mt < 4; mt++)
#pragma unroll
                for (int nt = 0; nt < 4; nt++)
                    mma_f16(acc[mt][nt], af[mt], bf[nt]);
        }

        if (more) {
            const int nxt = cur ^ 1;
            *(uint4*)&sh[nxt][lrow2 * KSH + lseg] = ra;
            *(uint4*)&sh[nxt][TILEH + lrow2 * KSH + lseg] = rb;
            __syncthreads();
            cur = nxt;
        }
    }

    if (!TRANS_RESID) {
#pragma unroll
        for (int mt = 0; mt < 4; mt++) {
            int m = bm + wm + 16 * mt + g;
#pragma unroll
            for (int nt = 0; nt < 4; nt++) {
                int n = bn + wn + 8 * nt + 2 * tig;
                *(float2*)&Cmat[(long)m * N + n] =
                    make_float2(acc[mt][nt][0], acc[mt][nt][1]);
                *(float2*)&Cmat[(long)(m + 8) * N + n] =
                    make_float2(acc[mt][nt][2], acc[mt][nt][3]);
            }
        }
    } else {
        // out is (N, M). Stage 32 n-rows (one warp-pair's n-range) per pass in
        // smem transposed as Cs[n'][m], stride 132, then coalesced float4 out.
        float* Cs = (float*)sh;    // 32*132*4 = 16896 B <= 24576
        __syncthreads();           // all warps done reading mma smem
#pragma unroll
        for (int p = 0; p < 4; p++) {
            if ((warp >> 1) == p) {
#pragma unroll
                for (int mt = 0; mt < 4; mt++) {
                    int m = wm + 16 * mt + g;
#pragma unroll
                    for (int nt = 0; nt < 4; nt++) {
                        int np = 8 * nt + 2 * tig;   // n within this 32-chunk
                        Cs[np * 132 + m]           = acc[mt][nt][0];
                        Cs[(np + 1) * 132 + m]     = acc[mt][nt][1];
                        Cs[np * 132 + m + 8]       = acc[mt][nt][2];
                        Cs[(np + 1) * 132 + m + 8] = acc[mt][nt][3];
                    }
                }
            }
            __syncthreads();
#pragma unroll
            for (int i = 0; i < 4; i++) {
                int idx = tid + 256 * i;          // 0..1023
                int row = idx >> 5;               // 0..31
                int m4 = (idx & 31) * 4;
                float4 c = *(float4*)&Cs[row * 132 + m4];
                long o = (long)(bn + p * 32 + row) * M + bm + m4;
                float4 r = *(const float4*)&resid[o];
                c.x += r.x; c.y += r.y; c.z += r.z; c.w += r.w;
                *(float4*)&Cmat[o] = c;
            }
            __syncthreads();
        }
    }
}

// ---------------------------------------------------------------------------
// Kernel 3: per-(window, head) RoPE + full 32x32 attention.
// Register-tiled fp32; output stored as fp16 for the out-GEMM.
// ---------------------------------------------------------------------------
__global__ void __launch_bounds__(256) attn_kernel(__half* __restrict__ att)
{
    const int w = blockIdx.x;
    const int h = blockIdx.y;
    const int t0 = w * WIN;
    const int tid = threadIdx.x;

    __shared__ float qs[32][66];   // stride 66 (even -> float2 aligned)
    __shared__ float ks[32][66];
    __shared__ float vs[32][68];   // stride 68 (mult of 4 -> float4 aligned)
    __shared__ float ls[32][33];

    for (int e = tid; e < 32 * 64; e += 256) {
        int n = e >> 6;
        int d = e & 63;
        long row = (long)(t0 + n) * QKVN;
        float q = g_qkv[row + h * 64 + d];
        float k = g_qkv[row + 1024 + h * 64 + d];
        float v = g_qkv[row + 2048 + h * 64 + d];
        float cs = g_rcos[e];
        float sn = g_rsin[e];
        float qr, kr;
        if (d < 32) {
            qr = -g_qkv[row + h * 64 + d + 32];
            kr = -g_qkv[row + 1024 + h * 64 + d + 32];
        } else {
            qr = g_qkv[row + h * 64 + d - 32];
            kr = g_qkv[row + 1024 + h * 64 + d - 32];
        }
        qs[n][d] = q * cs + qr * sn;
        ks[n][d] = k * cs + kr * sn;
        vs[n][d] = v;
    }
    __syncthreads();

    // QK^T: each thread computes a 2x2 logit tile with float2 LDS.
    {
        const int n0 = (tid >> 4) * 2;
        const int m0 = (tid & 15) * 2;
        float a00 = 0.f, a01 = 0.f, a10 = 0.f, a11 = 0.f;
#pragma unroll
        for (int d = 0; d < 64; d += 2) {
            float2 q0 = *(const float2*)&qs[n0][d];
            float2 q1 = *(const float2*)&qs[n0 + 1][d];
            float2 k0 = *(const float2*)&ks[m0][d];
            float2 k1 = *(const float2*)&ks[m0 + 1][d];
            a00 = fmaf(q0.x, k0.x, a00); a00 = fmaf(q0.y, k0.y, a00);
            a01 = fmaf(q0.x, k1.x, a01); a01 = fmaf(q0.y, k1.y, a01);
            a10 = fmaf(q1.x, k0.x, a10); a10 = fmaf(q1.y, k0.y, a10);
            a11 = fmaf(q1.x, k1.x, a11); a11 = fmaf(q1.y, k1.y, a11);
        }
        ls[n0][m0]         = a00 * 0.125f;
        ls[n0][m0 + 1]     = a01 * 0.125f;
        ls[n0 + 1][m0]     = a10 * 0.125f;
        ls[n0 + 1][m0 + 1] = a11 * 0.125f;
    }
    __syncthreads();

    const int warp = tid >> 5, lane = tid & 31;
    for (int r = warp; r < 32; r += 8) {
        float v = ls[r][lane];
        float mx = v;
#pragma unroll
        for (int o = 16; o; o >>= 1) mx = fmaxf(mx, __shfl_xor_sync(0xffffffffu, mx, o));
        float ev = __expf(v - mx);
        float sm = ev;
#pragma unroll
        for (int o = 16; o; o >>= 1) sm += __shfl_xor_sync(0xffffffffu, sm, o);
        ls[r][lane] = ev / sm;
    }
    __syncthreads();

    // PV: each thread computes 2 rows x 4 cols; stores fp16 (uint2).
    {
        const int n0 = (tid >> 4) * 2;
        const int d0 = (tid & 15) * 4;
        float4 o0 = make_float4(0.f, 0.f, 0.f, 0.f);
        float4 o1 = make_float4(0.f, 0.f, 0.f, 0.f);
#pragma unroll
        for (int m = 0; m < 32; m++) {
            float p0 = ls[n0][m];
            float p1 = ls[n0 + 1][m];
            float4 v4 = *(const float4*)&vs[m][d0];
            o0.x = fmaf(p0, v4.x, o0.x); o0.y = fmaf(p0, v4.y, o0.y);
            o0.z = fmaf(p0, v4.z, o0.z); o0.w = fmaf(p0, v4.w, o0.w);
            o1.x = fmaf(p1, v4.x, o1.x); o1.y = fmaf(p1, v4.y, o1.y);
            o1.z = fmaf(p1, v4.z, o1.z); o1.w = fmaf(p1, v4.w, o1.w);
        }
        *(uint2*)&att[(long)(t0 + n0) * CDIM + h * 64 + d0] =
            make_uint2(pack_h2(o0.x, o0.y), pack_h2(o0.z, o0.w));
        *(uint2*)&att[(long)(t0 + n0 + 1) * CDIM + h * 64 + d0] =
            make_uint2(pack_h2(o1.x, o1.y), pack_h2(o1.z, o1.w));
    }
}

// ---------------------------------------------------------------------------
extern "C" void kernel_launch(void* const* d_in, const int* in_sizes, int n_in,
                              void* d_out, int out_size)
{
    (void)in_sizes; (void)n_in; (void)out_size;
    const float* x     = (const float*)d_in[0];
    const float* wqkv  = (const float*)d_in[1];
    const float* wout  = (const float*)d_in[2];
    const float* gamma = (const float*)d_in[3];
    const float* beta  = (const float*)d_in[4];
    float* out = (float*)d_out;

    float* qkv;
    __half *nh, *att_h, *wq_h, *wo_h;
    cudaGetSymbolAddress((void**)&qkv, g_qkv);
    cudaGetSymbolAddress((void**)&nh, g_nh);
    cudaGetSymbolAddress((void**)&att_h, g_att_h);
    cudaGetSymbolAddress((void**)&wq_h, g_wqkv_h);
    cudaGetSymbolAddress((void**)&wo_h, g_wout_h);

    // 0. RoPE table + weight fp16 conversion
    rope_init_kernel<<<8, 256>>>();
    w16_kernel<<<1024, 256>>>(wqkv, wout);

    // 1. LayerNorm -> g_nh (fp16, (T, C))
    ln_kernel<<<TDIM / WIN, 256>>>(x, gamma, beta, nh);

    // 2. QKV GEMM: (T, C) x (3C, C)^T -> (T, 3C) fp32
    tgemm_kernel<false><<<dim3(TDIM / 128, QKVN / 128), 256>>>(
        nh, wq_h, qkv, nullptr, TDIM, QKVN, CDIM);

    // 3. RoPE + windowed attention -> g_att_h (fp16, (T, C))
    attn_kernel<<<dim3(TDIM / WIN, NHEADS), 256>>>(att_h);

    // 4. Output GEMM + transposed residual epilogue -> d_out (C, T) fp32
    tgemm_kernel<true><<<dim3(TDIM / 128, CDIM / 128), 256>>>(
        att_h, wo_h, out, x, TDIM, CDIM, CDIM);
}

// round 16
// speedup vs baseline: 4.4705x; 1.0504x over previous
#include <cuda_runtime.h>
#include <cuda_fp16.h>
#include <cuda_bf16.h>
#include <math.h>
#include <stdint.h>

#define TDIM 16384
#define CDIM 1024
#define WIN 32
#define DHEAD 64
#define NHEADS 16
#define QKVN 3072

// Scratch (device globals; no allocation allowed).
__device__ float  g_qkv[TDIM * QKVN];        // (T, 3C) fp32, 192 MB
__device__ __half g_nh[TDIM * CDIM];         // normed (T, C) fp16, 32 MB
__device__ __half g_att_h[TDIM * CDIM];      // attention out (T, C) fp16, 32 MB
__device__ __half g_wqkv_h[QKVN * CDIM];     // w_qkv fp16, 6 MB
__device__ __half g_wout_h[CDIM * CDIM];     // w_out fp16, 2 MB
__device__ float  g_rcos[WIN * DHEAD];       // RoPE cos table (32 x 64)
__device__ float  g_rsin[WIN * DHEAD];       // RoPE sin table

// ---------------------------------------------------------------------------
// PTX helpers
// ---------------------------------------------------------------------------
__device__ __forceinline__ void mma_f16(float* c, const uint32_t* a, const uint32_t* b) {
    asm volatile(
        "mma.sync.aligned.m16n8k16.row.col.f32.f16.f16.f32 "
        "{%0,%1,%2,%3}, {%4,%5,%6,%7}, {%8,%9}, {%0,%1,%2,%3};"
        : "+f"(c[0]), "+f"(c[1]), "+f"(c[2]), "+f"(c[3])
        : "r"(a[0]), "r"(a[1]), "r"(a[2]), "r"(a[3]), "r"(b[0]), "r"(b[1]));
}

__device__ __forceinline__ void ldsm_x4(uint32_t& r0, uint32_t& r1,
                                        uint32_t& r2, uint32_t& r3, uint32_t addr) {
    asm volatile("ldmatrix.sync.aligned.m8n8.x4.shared.b16 {%0,%1,%2,%3}, [%4];"
        : "=r"(r0), "=r"(r1), "=r"(r2), "=r"(r3) : "r"(addr));
}

__device__ __forceinline__ uint32_t pack_h2(float x, float y) {
    __half2 h = __floats2half2_rn(x, y);
    return *(uint32_t*)&h;
}

// ---------------------------------------------------------------------------
// Kernel 0a: RoPE table init (32 positions x 64 dims).
// ---------------------------------------------------------------------------
__global__ void rope_init_kernel() {
    int i = blockIdx.x * blockDim.x + threadIdx.x;   // 0..2047
    int n = i >> 6;
    int d = i & 63;
    const float LOG1E4 = 9.210340371976184f;
    float inv = expf(-((float)(d & 31) / 32.f) * LOG1E4);
    float ang = (float)n * inv;
    float sn, cs;
    sincosf(ang, &sn, &cs);
    g_rcos[i] = cs;
    g_rsin[i] = sn;
}

// ---------------------------------------------------------------------------
// Kernel 0b: weight fp32 -> fp16 conversion (one shot per launch, ~5us).
// ---------------------------------------------------------------------------
__global__ void __launch_bounds__(256) w16_kernel(
    const float* __restrict__ wqkv, const float* __restrict__ wout)
{
    const int NQ = QKVN * CDIM;
    const int NO = CDIM * CDIM;
    for (int i = blockIdx.x * blockDim.x + threadIdx.x; i < NQ;
         i += gridDim.x * blockDim.x)
        g_wqkv_h[i] = __float2half_rn(wqkv[i]);
    for (int i = blockIdx.x * blockDim.x + threadIdx.x; i < NO;
         i += gridDim.x * blockDim.x)
        g_wout_h[i] = __float2half_rn(wout[i]);
}

// ---------------------------------------------------------------------------
// Kernel 1: LayerNorm over channel dim. x is (C, T). Output (T, C) fp16.
// ---------------------------------------------------------------------------
__global__ void __launch_bounds__(256) ln_kernel(
    const float* __restrict__ x,
    const float* __restrict__ gamma,
    const float* __restrict__ beta,
    __half* __restrict__ out)
{
    const int t0 = blockIdx.x * WIN;
    const int tx = threadIdx.x & 31;
    const int ty = threadIdx.x >> 5;

    __shared__ float rs[8][32];
    __shared__ float rs2[8][32];
    __shared__ float s_mu[32];
    __shared__ float s_rsig[32];
    __shared__ float tile[32][33];

    float s = 0.f, s2 = 0.f;
    const int t = t0 + tx;
    for (int c = ty; c < CDIM; c += 8) {
        float v = x[c * TDIM + t];
        s += v; s2 += v * v;
    }
    rs[ty][tx] = s; rs2[ty][tx] = s2;
    __syncthreads();
    if (ty == 0) {
        float a = 0.f, b = 0.f;
#pragma unroll
        for (int j = 0; j < 8; j++) { a += rs[j][tx]; b += rs2[j][tx]; }
        float mu = a * (1.0f / CDIM);
        float var = b * (1.0f / CDIM) - mu * mu;
        s_mu[tx] = mu;
        s_rsig[tx] = rsqrtf(var + 1e-5f);
    }
    __syncthreads();

    for (int c0 = 0; c0 < CDIM; c0 += 32) {
        for (int r = ty; r < 32; r += 8)
            tile[r][tx] = x[(c0 + r) * TDIM + t0 + tx];
        __syncthreads();
        float g = gamma[c0 + tx];
        float be = beta[c0 + tx];
        for (int tl = ty; tl < 32; tl += 8) {
            float v = tile[tx][tl];
            out[(t0 + tl) * CDIM + c0 + tx] =
                __float2half_rn((v - s_mu[tl]) * s_rsig[tl] * g + be);
        }
        __syncthreads();
    }
}

// ---------------------------------------------------------------------------
// FP16 tensor-core GEMM (f32 accumulate):  C[m][n] = sum_k A[m][k] * B[n][k]
//   A: (M,K) fp16 row-major, B: (N,K) fp16 row-major (pre-converted).
// 128x128 block tile, Ktile=16, 128 threads (4 warps, 2x2), warp tile 64x64,
// 4x8 m16n8k16 microtiles via ldmatrix.x4 (8 LDSM : 32 MMA per warp-ktile;
// fragment replication A x2 / B x2). Smem fp16 [row][k] stride 24 halves.
// Double-buffered; 2 uint4 LDG + 2 uint4 STS per matrix per thread per ktile.
// TRANS_RESID: out[n*M+m] = acc + resid[n*M+m] (fp32), staged 32 rows/pass.
// ---------------------------------------------------------------------------
#define KSH 24                    // halves per smem row (48 B)
#define TILEH (128 * KSH)         // 3072 halves per matrix tile

template <bool TRANS_RESID>
__global__ void __launch_bounds__(128) tgemm_kernel(
    const __half* __restrict__ A,
    const __half* __restrict__ B,
    float* __restrict__ Cmat,
    const float* __restrict__ resid,
    int M, int N, int K)
{
    __shared__ __align__(16) __half sh[2][2 * TILEH];   // 24576 B, static

    const int bm = blockIdx.x * 128;
    const int bn = blockIdx.y * 128;
    const int tid = threadIdx.x;
    const int warp = tid >> 5;
    const int lane = tid & 31;
    const int g = lane >> 2;       // 0..7
    const int tig = lane & 3;      // 0..3
    const int wm = (warp & 1) * 64;
    const int wn = (warp >> 1) * 64;

    // ldmatrix per-lane address offsets (in halves, relative to tile base)
    const int l8 = lane & 7;
    const int sel = lane >> 3;       // 0..3
    int aoff[4], boff[4];
#pragma unroll
    for (int mt = 0; mt < 4; mt++)
        aoff[mt] = (wm + 16 * mt + l8 + (sel & 1) * 8) * KSH + (sel >> 1) * 8;
#pragma unroll
    for (int j = 0; j < 4; j++)
        boff[j] = (wn + 16 * j + (sel >> 1) * 8 + l8) * KSH + (sel & 1) * 8;

    float acc[4][8][4];
#pragma unroll
    for (int i = 0; i < 4; i++)
#pragma unroll
        for (int j = 0; j < 8; j++)
#pragma unroll
            for (int r = 0; r < 4; r++) acc[i][j][r] = 0.f;

    uint4 ra[2], rb[2];

    // Loader mapping: c = tid + 128*i -> row = c>>1, seg = (c&1)*8 halves.
    // Prologue: K-tile 0 -> registers -> smem buffer 0.
#pragma unroll
    for (int i = 0; i < 2; i++) {
        int c = tid + 128 * i;
        int row = c >> 1, seg = (c & 1) * 8;
        ra[i] = *(const uint4*)&A[(long)(bm + row) * K + seg];
        rb[i] = *(const uint4*)&B[(long)(bn + row) * K + seg];
    }
#pragma unroll
    for (int i = 0; i < 2; i++) {
        int c = tid + 128 * i;
        int row = c >> 1, seg = (c & 1) * 8;
        *(uint4*)&sh[0][row * KSH + seg] = ra[i];
        *(uint4*)&sh[0][TILEH + row * KSH + seg] = rb[i];
    }
    __syncthreads();
    int cur = 0;

    const int NK = K >> 4;
    for (int kt = 0; kt < NK; kt++) {
        const bool more = (kt + 1 < NK);
        if (more) {
            const int k0 = (kt + 1) * 16;
#pragma unroll
            for (int i = 0; i < 2; i++) {
                int c = tid + 128 * i;
                int row = c >> 1, seg = (c & 1) * 8;
                ra[i] = *(const uint4*)&A[(long)(bm + row) * K + k0 + seg];
                rb[i] = *(const uint4*)&B[(long)(bn + row) * K + k0 + seg];
            }
        }

        {
            const uint32_t a_base = (uint32_t)__cvta_generic_to_shared(sh[cur]);
            const uint32_t b_base = a_base + TILEH * 2;
            uint32_t af[4][4], bf[8][2];
#pragma unroll
            for (int mt = 0; mt < 4; mt++)
                ldsm_x4(af[mt][0], af[mt][1], af[mt][2], af[mt][3],
                        a_base + 2 * aoff[mt]);
#pragma unroll
            for (int j = 0; j < 4; j++)
                ldsm_x4(bf[2*j][0], bf[2*j][1], bf[2*j+1][0], bf[2*j+1][1],
                        b_base + 2 * boff[j]);
#pragma unroll
            for (int mt = 0; mt < 4; mt++)
#pragma unroll
                for (int nt = 0; nt < 8; nt++)
                    mma_f16(acc[mt][nt], af[mt], bf[nt]);
        }

        if (more) {
            const int nxt = cur ^ 1;
#pragma unroll
            for (int i = 0; i < 2; i++) {
                int c = tid + 128 * i;
                int row = c >> 1, seg = (c & 1) * 8;
                *(uint4*)&sh[nxt][row * KSH + seg] = ra[i];
                *(uint4*)&sh[nxt][TILEH + row * KSH + seg] = rb[i];
            }
            __syncthreads();
            cur = nxt;
        }
    }

    if (!TRANS_RESID) {
#pragma unroll
        for (int mt = 0; mt < 4; mt++) {
            int m = bm + wm + 16 * mt + g;
#pragma unroll
            for (int nt = 0; nt < 8; nt++) {
                int n = bn + wn + 8 * nt + 2 * tig;
                *(float2*)&Cmat[(long)m * N + n] =
                    make_float2(acc[mt][nt][0], acc[mt][nt][1]);
                *(float2*)&Cmat[(long)(m + 8) * N + n] =
                    make_float2(acc[mt][nt][2], acc[mt][nt][3]);
            }
        }
    } else {
        // out is (N, M). 4 chunks of 32 n-rows; chunk p is held by the warp
        // column (p>>1), nt range (p&1)*4..+3. Staged transposed in smem as
        // Cs[n'][m] stride 132, then coalesced float4 rows + residual.
        float* Cs = (float*)sh;    // 32*132*4 = 16896 B <= 24576
        __syncthreads();           // all warps done reading mma smem
#pragma unroll
        for (int p = 0; p < 4; p++) {
            if ((warp >> 1) == (p >> 1)) {
                const int ntb = (p & 1) * 4;
#pragma unroll
                for (int mt = 0; mt < 4; mt++) {
                    int m = wm + 16 * mt + g;
#pragma unroll
                    for (int nt = 0; nt < 4; nt++) {
                        int np = 8 * nt + 2 * tig;   // n within this 32-chunk
                        const float* c = acc[mt][ntb + nt];
                        Cs[np * 132 + m]           = c[0];
                        Cs[(np + 1) * 132 + m]     = c[1];
                        Cs[np * 132 + m + 8]       = c[2];
                        Cs[(np + 1) * 132 + m + 8] = c[3];
                    }
                }
            }
            __syncthreads();
#pragma unroll
            for (int i = 0; i < 8; i++) {
                int idx = tid + 128 * i;          // 0..1023
                int row = idx >> 5;               // 0..31
                int m4 = (idx & 31) * 4;
                float4 c = *(float4*)&Cs[row * 132 + m4];
                long o = (long)(bn + p * 32 + row) * M + bm + m4;
                float4 r = *(const float4*)&resid[o];
                c.x += r.x; c.y += r.y; c.z += r.z; c.w += r.w;
                *(float4*)&Cmat[o] = c;
            }
            __syncthreads();
        }
    }
}

// ---------------------------------------------------------------------------
// Kernel 3: per-(window, head) RoPE + full 32x32 attention.
// Register-tiled fp32; output stored as fp16 for the out-GEMM.
// ---------------------------------------------------------------------------
__global__ void __launch_bounds__(256) attn_kernel(__half* __restrict__ att)
{
    const int w = blockIdx.x;
    const int h = blockIdx.y;
    const int t0 = w * WIN;
    const int tid = threadIdx.x;

    __shared__ float qs[32][66];   // stride 66 (even -> float2 aligned)
    __shared__ float ks[32][66];
    __shared__ float vs[32][68];   // stride 68 (mult of 4 -> float4 aligned)
    __shared__ float ls[32][33];

    for (int e = tid; e < 32 * 64; e += 256) {
        int n = e >> 6;
        int d = e & 63;
        long row = (long)(t0 + n) * QKVN;
        float q = g_qkv[row + h * 64 + d];
        float k = g_qkv[row + 1024 + h * 64 + d];
        float v = g_qkv[row + 2048 + h * 64 + d];
        float cs = g_rcos[e];
        float sn = g_rsin[e];
        float qr, kr;
        if (d < 32) {
            qr = -g_qkv[row + h * 64 + d + 32];
            kr = -g_qkv[row + 1024 + h * 64 + d + 32];
        } else {
            qr = g_qkv[row + h * 64 + d - 32];
            kr = g_qkv[row + 1024 + h * 64 + d - 32];
        }
        qs[n][d] = q * cs + qr * sn;
        ks[n][d] = k * cs + kr * sn;
        vs[n][d] = v;
    }
    __syncthreads();

    // QK^T: each thread computes a 2x2 logit tile with float2 LDS.
    {
        const int n0 = (tid >> 4) * 2;
        const int m0 = (tid & 15) * 2;
        float a00 = 0.f, a01 = 0.f, a10 = 0.f, a11 = 0.f;
#pragma unroll
        for (int d = 0; d < 64; d += 2) {
            float2 q0 = *(const float2*)&qs[n0][d];
            float2 q1 = *(const float2*)&qs[n0 + 1][d];
            float2 k0 = *(const float2*)&ks[m0][d];
            float2 k1 = *(const float2*)&ks[m0 + 1][d];
            a00 = fmaf(q0.x, k0.x, a00); a00 = fmaf(q0.y, k0.y, a00);
            a01 = fmaf(q0.x, k1.x, a01); a01 = fmaf(q0.y, k1.y, a01);
            a10 = fmaf(q1.x, k0.x, a10); a10 = fmaf(q1.y, k0.y, a10);
            a11 = fmaf(q1.x, k1.x, a11); a11 = fmaf(q1.y, k1.y, a11);
        }
        ls[n0][m0]         = a00 * 0.125f;
        ls[n0][m0 + 1]     = a01 * 0.125f;
        ls[n0 + 1][m0]     = a10 * 0.125f;
        ls[n0 + 1][m0 + 1] = a11 * 0.125f;
    }
    __syncthreads();

    const int warp = tid >> 5, lane = tid & 31;
    for (int r = warp; r < 32; r += 8) {
        float v = ls[r][lane];
        float mx = v;
#pragma unroll
        for (int o = 16; o; o >>= 1) mx = fmaxf(mx, __shfl_xor_sync(0xffffffffu, mx, o));
        float ev = __expf(v - mx);
        float sm = ev;
#pragma unroll
        for (int o = 16; o; o >>= 1) sm += __shfl_xor_sync(0xffffffffu, sm, o);
        ls[r][lane] = ev / sm;
    }
    __syncthreads();

    // PV: each thread computes 2 rows x 4 cols; stores fp16 (uint2).
    {
        const int n0 = (tid >> 4) * 2;
        const int d0 = (tid & 15) * 4;
        float4 o0 = make_float4(0.f, 0.f, 0.f, 0.f);
        float4 o1 = make_float4(0.f, 0.f, 0.f, 0.f);
#pragma unroll
        for (int m = 0; m < 32; m++) {
            float p0 = ls[n0][m];
            float p1 = ls[n0 + 1][m];
            float4 v4 = *(const float4*)&vs[m][d0];
            o0.x = fmaf(p0, v4.x, o0.x); o0.y = fmaf(p0, v4.y, o0.y);
            o0.z = fmaf(p0, v4.z, o0.z); o0.w = fmaf(p0, v4.w, o0.w);
            o1.x = fmaf(p1, v4.x, o1.x); o1.y = fmaf(p1, v4.y, o1.y);
            o1.z = fmaf(p1, v4.z, o1.z); o1.w = fmaf(p1, v4.w, o1.w);
        }
        *(uint2*)&att[(long)(t0 + n0) * CDIM + h * 64 + d0] =
            make_uint2(pack_h2(o0.x, o0.y), pack_h2(o0.z, o0.w));
        *(uint2*)&att[(long)(t0 + n0 + 1) * CDIM + h * 64 + d0] =
            make_uint2(pack_h2(o1.x, o1.y), pack_h2(o1.z, o1.w));
    }
}

// ---------------------------------------------------------------------------
extern "C" void kernel_launch(void* const* d_in, const int* in_sizes, int n_in,
                              void* d_out, int out_size)
{
    (void)in_sizes; (void)n_in; (void)out_size;
    const float* x     = (const float*)d_in[0];
    const float* wqkv  = (const float*)d_in[1];
    const float* wout  = (const float*)d_in[2];
    const float* gamma = (const float*)d_in[3];
    const float* beta  = (const float*)d_in[4];
    float* out = (float*)d_out;

    float* qkv;
    __half *nh, *att_h, *wq_h, *wo_h;
    cudaGetSymbolAddress((void**)&qkv, g_qkv);
    cudaGetSymbolAddress((void**)&nh, g_nh);
    cudaGetSymbolAddress((void**)&att_h, g_att_h);
    cudaGetSymbolAddress((void**)&wq_h, g_wqkv_h);
    cudaGetSymbolAddress((void**)&wo_h, g_wout_h);

    // 0. RoPE table + weight fp16 conversion
    rope_init_kernel<<<8, 256>>>();
    w16_kernel<<<1024, 256>>>(wqkv, wout);

    // 1. LayerNorm -> g_nh (fp16, (T, C))
    ln_kernel<<<TDIM / WIN, 256>>>(x, gamma, beta, nh);

    // 2. QKV GEMM: (T, C) x (3C, C)^T -> (T, 3C) fp32
    tgemm_kernel<false><<<dim3(TDIM / 128, QKVN / 128), 128>>>(
        nh, wq_h, qkv, nullptr, TDIM, QKVN, CDIM);

    // 3. RoPE + windowed attention -> g_att_h (fp16, (T, C))
    attn_kernel<<<dim3(TDIM / WIN, NHEADS), 256>>>(att_h);

    // 4. Output GEMM + transposed residual epilogue -> d_out (C, T) fp32
    tgemm_kernel<true><<<dim3(TDIM / 128, CDIM / 128), 128>>>(
        att_h, wo_h, out, x, TDIM, CDIM, CDIM);
}

// round 17
// speedup vs baseline: 4.9832x; 1.1147x over previous
#include <cuda_runtime.h>
#include <cuda_fp16.h>
#include <cuda_bf16.h>
#include <math.h>
#include <stdint.h>

#define TDIM 16384
#define CDIM 1024
#define WIN 32
#define DHEAD 64
#define NHEADS 16
#define QKVN 3072

// Scratch (device globals; no allocation allowed).
__device__ float  g_qkv[TDIM * QKVN];        // (T, 3C) fp32, 192 MB
__device__ __half g_nh[TDIM * CDIM];         // normed (T, C) fp16, 32 MB
__device__ __half g_att_h[TDIM * CDIM];      // attention out (T, C) fp16, 32 MB
__device__ __half g_wqkv_h[QKVN * CDIM];     // w_qkv fp16, 6 MB
__device__ __half g_wout_h[CDIM * CDIM];     // w_out fp16, 2 MB
__device__ float  g_rcos[WIN * DHEAD];       // RoPE cos table (32 x 64)
__device__ float  g_rsin[WIN * DHEAD];       // RoPE sin table

// ---------------------------------------------------------------------------
// PTX helpers
// ---------------------------------------------------------------------------
__device__ __forceinline__ void mma_f16(float* c, const uint32_t* a, const uint32_t* b) {
    asm volatile(
        "mma.sync.aligned.m16n8k16.row.col.f32.f16.f16.f32 "
        "{%0,%1,%2,%3}, {%4,%5,%6,%7}, {%8,%9}, {%0,%1,%2,%3};"
        : "+f"(c[0]), "+f"(c[1]), "+f"(c[2]), "+f"(c[3])
        : "r"(a[0]), "r"(a[1]), "r"(a[2]), "r"(a[3]), "r"(b[0]), "r"(b[1]));
}

__device__ __forceinline__ void ldsm_x4(uint32_t& r0, uint32_t& r1,
                                        uint32_t& r2, uint32_t& r3, uint32_t addr) {
    asm volatile("ldmatrix.sync.aligned.m8n8.x4.shared.b16 {%0,%1,%2,%3}, [%4];"
        : "=r"(r0), "=r"(r1), "=r"(r2), "=r"(r3) : "r"(addr));
}

__device__ __forceinline__ void cp16(uint32_t saddr, const void* g) {
    asm volatile("cp.async.cg.shared.global [%0], [%1], 16;" :: "r"(saddr), "l"(g));
}
#define CP_COMMIT() asm volatile("cp.async.commit_group;" ::: "memory")
#define CP_WAIT1()  asm volatile("cp.async.wait_group 1;" ::: "memory")

__device__ __forceinline__ uint32_t pack_h2(float x, float y) {
    __half2 h = __floats2half2_rn(x, y);
    return *(uint32_t*)&h;
}

// ---------------------------------------------------------------------------
// Kernel 0a: RoPE table init (32 positions x 64 dims).
// ---------------------------------------------------------------------------
__global__ void rope_init_kernel() {
    int i = blockIdx.x * blockDim.x + threadIdx.x;   // 0..2047
    int n = i >> 6;
    int d = i & 63;
    const float LOG1E4 = 9.210340371976184f;
    float inv = expf(-((float)(d & 31) / 32.f) * LOG1E4);
    float ang = (float)n * inv;
    float sn, cs;
    sincosf(ang, &sn, &cs);
    g_rcos[i] = cs;
    g_rsin[i] = sn;
}

// ---------------------------------------------------------------------------
// Kernel 0b: weight fp32 -> fp16 conversion (one shot per launch, ~5us).
// ---------------------------------------------------------------------------
__global__ void __launch_bounds__(256) w16_kernel(
    const float* __restrict__ wqkv, const float* __restrict__ wout)
{
    const int NQ = QKVN * CDIM;
    const int NO = CDIM * CDIM;
    for (int i = blockIdx.x * blockDim.x + threadIdx.x; i < NQ;
         i += gridDim.x * blockDim.x)
        g_wqkv_h[i] = __float2half_rn(wqkv[i]);
    for (int i = blockIdx.x * blockDim.x + threadIdx.x; i < NO;
         i += gridDim.x * blockDim.x)
        g_wout_h[i] = __float2half_rn(wout[i]);
}

// ---------------------------------------------------------------------------
// Kernel 1: LayerNorm over channel dim. x is (C, T). Output (T, C) fp16.
// ---------------------------------------------------------------------------
__global__ void __launch_bounds__(256) ln_kernel(
    const float* __restrict__ x,
    const float* __restrict__ gamma,
    const float* __restrict__ beta,
    __half* __restrict__ out)
{
    const int t0 = blockIdx.x * WIN;
    const int tx = threadIdx.x & 31;
    const int ty = threadIdx.x >> 5;

    __shared__ float rs[8][32];
    __shared__ float rs2[8][32];
    __shared__ float s_mu[32];
    __shared__ float s_rsig[32];
    __shared__ float tile[32][33];

    float s = 0.f, s2 = 0.f;
    const int t = t0 + tx;
    for (int c = ty; c < CDIM; c += 8) {
        float v = x[c * TDIM + t];
        s += v; s2 += v * v;
    }
    rs[ty][tx] = s; rs2[ty][tx] = s2;
    __syncthreads();
    if (ty == 0) {
        float a = 0.f, b = 0.f;
#pragma unroll
        for (int j = 0; j < 8; j++) { a += rs[j][tx]; b += rs2[j][tx]; }
        float mu = a * (1.0f / CDIM);
        float var = b * (1.0f / CDIM) - mu * mu;
        s_mu[tx] = mu;
        s_rsig[tx] = rsqrtf(var + 1e-5f);
    }
    __syncthreads();

    for (int c0 = 0; c0 < CDIM; c0 += 32) {
        for (int r = ty; r < 32; r += 8)
            tile[r][tx] = x[(c0 + r) * TDIM + t0 + tx];
        __syncthreads();
        float g = gamma[c0 + tx];
        float be = beta[c0 + tx];
        for (int tl = ty; tl < 32; tl += 8) {
            float v = tile[tx][tl];
            out[(t0 + tl) * CDIM + c0 + tx] =
                __float2half_rn((v - s_mu[tl]) * s_rsig[tl] * g + be);
        }
        __syncthreads();
    }
}

// ---------------------------------------------------------------------------
// FP16 tensor-core GEMM (f32 accumulate):  C[m][n] = sum_k A[m][k] * B[n][k]
//   A: (M,K) fp16 row-major, B: (N,K) fp16 row-major (pre-converted).
// 128x128 block tile, Ktile=16, 128 threads (4 warps, 2x2), warp tile 64x64,
// 4x8 m16n8k16 microtiles via ldmatrix.x4. Smem fp16 [row][k] stride 24
// halves. 3-stage cp.async.cg pipeline (no LDG/STS register round-trip;
// wait_group 1 keeps two tile loads in flight).
// TRANS_RESID: out[n*M+m] = acc + resid[n*M+m] (fp32), staged 32 rows/pass.
// ---------------------------------------------------------------------------
#define KSH 24                    // halves per smem row (48 B)
#define TILEH (128 * KSH)         // 3072 halves per matrix tile
#define NSTAGE 3

template <bool TRANS_RESID>
__global__ void __launch_bounds__(128) tgemm_kernel(
    const __half* __restrict__ A,
    const __half* __restrict__ B,
    float* __restrict__ Cmat,
    const float* __restrict__ resid,
    int M, int N, int K)
{
    __shared__ __align__(16) __half sh[NSTAGE][2 * TILEH];   // 36864 B, static

    const int bm = blockIdx.x * 128;
    const int bn = blockIdx.y * 128;
    const int tid = threadIdx.x;
    const int warp = tid >> 5;
    const int lane = tid & 31;
    const int g = lane >> 2;       // 0..7
    const int tig = lane & 3;      // 0..3
    const int wm = (warp & 1) * 64;
    const int wn = (warp >> 1) * 64;

    // ldmatrix per-lane address offsets (in halves, relative to tile base)
    const int l8 = lane & 7;
    const int sel = lane >> 3;       // 0..3
    int aoff[4], boff[4];
#pragma unroll
    for (int mt = 0; mt < 4; mt++)
        aoff[mt] = (wm + 16 * mt + l8 + (sel & 1) * 8) * KSH + (sel >> 1) * 8;
#pragma unroll
    for (int j = 0; j < 4; j++)
        boff[j] = (wn + 16 * j + (sel >> 1) * 8 + l8) * KSH + (sel & 1) * 8;

    float acc[4][8][4];
#pragma unroll
    for (int i = 0; i < 4; i++)
#pragma unroll
        for (int j = 0; j < 8; j++)
#pragma unroll
            for (int r = 0; r < 4; r++) acc[i][j][r] = 0.f;

    // Loader mapping: c = tid + 128*i -> row = c>>1, seg = (c&1)*8 halves.
    const uint32_t sh_base = (uint32_t)__cvta_generic_to_shared(sh);

    const int NK = K >> 4;

    // issue_stage(kt, buf): cp.async both tiles of K-tile kt into stage buf.
    // (expanded inline at each call site below)
#define ISSUE_STAGE(KT, BUF)                                                   \
    do {                                                                       \
        const int k0_ = (KT) * 16;                                             \
        const uint32_t sb_ = sh_base + (BUF) * (2 * TILEH * 2);                \
        _Pragma("unroll")                                                      \
        for (int i_ = 0; i_ < 2; i_++) {                                       \
            int c_ = tid + 128 * i_;                                           \
            int row_ = c_ >> 1, seg_ = (c_ & 1) * 8;                           \
            cp16(sb_ + (row_ * KSH + seg_) * 2,                                \
                 &A[(long)(bm + row_) * K + k0_ + seg_]);                      \
            cp16(sb_ + (TILEH + row_ * KSH + seg_) * 2,                        \
                 &B[(long)(bn + row_) * K + k0_ + seg_]);                      \
        }                                                                      \
        CP_COMMIT();                                                           \
    } while (0)

    ISSUE_STAGE(0, 0);
    ISSUE_STAGE(1, 1);

    for (int kt = 0; kt < NK; kt++) {
        CP_WAIT1();
        __syncthreads();

        {
            const int buf = kt % NSTAGE;
            const uint32_t a_base = sh_base + buf * (2 * TILEH * 2);
            const uint32_t b_base = a_base + TILEH * 2;
            uint32_t af[4][4], bf[8][2];
#pragma unroll
            for (int mt = 0; mt < 4; mt++)
                ldsm_x4(af[mt][0], af[mt][1], af[mt][2], af[mt][3],
                        a_base + 2 * aoff[mt]);
#pragma unroll
            for (int j = 0; j < 4; j++)
                ldsm_x4(bf[2*j][0], bf[2*j][1], bf[2*j+1][0], bf[2*j+1][1],
                        b_base + 2 * boff[j]);
#pragma unroll
            for (int mt = 0; mt < 4; mt++)
#pragma unroll
                for (int nt = 0; nt < 8; nt++)
                    mma_f16(acc[mt][nt], af[mt], bf[nt]);
        }

        if (kt + 2 < NK) {
            ISSUE_STAGE(kt + 2, (kt + 2) % NSTAGE);
        } else {
            CP_COMMIT();   // keep group count advancing for the final waits
        }
    }
#undef ISSUE_STAGE

    if (!TRANS_RESID) {
#pragma unroll
        for (int mt = 0; mt < 4; mt++) {
            int m = bm + wm + 16 * mt + g;
#pragma unroll
            for (int nt = 0; nt < 8; nt++) {
                int n = bn + wn + 8 * nt + 2 * tig;
                *(float2*)&Cmat[(long)m * N + n] =
                    make_float2(acc[mt][nt][0], acc[mt][nt][1]);
                *(float2*)&Cmat[(long)(m + 8) * N + n] =
                    make_float2(acc[mt][nt][2], acc[mt][nt][3]);
            }
        }
    } else {
        // out is (N, M). 4 chunks of 32 n-rows; chunk p is held by the warp
        // column (p>>1), nt range (p&1)*4..+3. Staged transposed in smem as
        // Cs[n'][m] stride 132, then coalesced float4 rows + residual.
        float* Cs = (float*)sh;    // 32*132*4 = 16896 B <= 36864
        __syncthreads();           // all warps done reading mma smem
#pragma unroll
        for (int p = 0; p < 4; p++) {
            if ((warp >> 1) == (p >> 1)) {
                const int ntb = (p & 1) * 4;
#pragma unroll
                for (int mt = 0; mt < 4; mt++) {
                    int m = wm + 16 * mt + g;
#pragma unroll
                    for (int nt = 0; nt < 4; nt++) {
                        int np = 8 * nt + 2 * tig;   // n within this 32-chunk
                        const float* c = acc[mt][ntb + nt];
                        Cs[np * 132 + m]           = c[0];
                        Cs[(np + 1) * 132 + m]     = c[1];
                        Cs[np * 132 + m + 8]       = c[2];
                        Cs[(np + 1) * 132 + m + 8] = c[3];
                    }
                }
            }
            __syncthreads();
#pragma unroll
            for (int i = 0; i < 8; i++) {
                int idx = tid + 128 * i;          // 0..1023
                int row = idx >> 5;               // 0..31
                int m4 = (idx & 31) * 4;
                float4 c = *(float4*)&Cs[row * 132 + m4];
                long o = (long)(bn + p * 32 + row) * M + bm + m4;
                float4 r = *(const float4*)&resid[o];
                c.x += r.x; c.y += r.y; c.z += r.z; c.w += r.w;
                *(float4*)&Cmat[o] = c;
            }
            __syncthreads();
        }
    }
}

// ---------------------------------------------------------------------------
// Kernel 3: per-(window, head) RoPE + full 32x32 attention.
// Register-tiled fp32; output stored as fp16 for the out-GEMM.
// ---------------------------------------------------------------------------
__global__ void __launch_bounds__(256) attn_kernel(__half* __restrict__ att)
{
    const int w = blockIdx.x;
    const int h = blockIdx.y;
    const int t0 = w * WIN;
    const int tid = threadIdx.x;

    __shared__ float qs[32][66];   // stride 66 (even -> float2 aligned)
    __shared__ float ks[32][66];
    __shared__ float vs[32][68];   // stride 68 (mult of 4 -> float4 aligned)
    __shared__ float ls[32][33];

    for (int e = tid; e < 32 * 64; e += 256) {
        int n = e >> 6;
        int d = e & 63;
        long row = (long)(t0 + n) * QKVN;
        float q = g_qkv[row + h * 64 + d];
        float k = g_qkv[row + 1024 + h * 64 + d];
        float v = g_qkv[row + 2048 + h * 64 + d];
        float cs = g_rcos[e];
        float sn = g_rsin[e];
        float qr, kr;
        if (d < 32) {
            qr = -g_qkv[row + h * 64 + d + 32];
            kr = -g_qkv[row + 1024 + h * 64 + d + 32];
        } else {
            qr = g_qkv[row + h * 64 + d - 32];
            kr = g_qkv[row + 1024 + h * 64 + d - 32];
        }
        qs[n][d] = q * cs + qr * sn;
        ks[n][d] = k * cs + kr * sn;
        vs[n][d] = v;
    }
    __syncthreads();

    // QK^T: each thread computes a 2x2 logit tile with float2 LDS.
    {
        const int n0 = (tid >> 4) * 2;
        const int m0 = (tid & 15) * 2;
        float a00 = 0.f, a01 = 0.f, a10 = 0.f, a11 = 0.f;
#pragma unroll
        for (int d = 0; d < 64; d += 2) {
            float2 q0 = *(const float2*)&qs[n0][d];
            float2 q1 = *(const float2*)&qs[n0 + 1][d];
            float2 k0 = *(const float2*)&ks[m0][d];
            float2 k1 = *(const float2*)&ks[m0 + 1][d];
            a00 = fmaf(q0.x, k0.x, a00); a00 = fmaf(q0.y, k0.y, a00);
            a01 = fmaf(q0.x, k1.x, a01); a01 = fmaf(q0.y, k1.y, a01);
            a10 = fmaf(q1.x, k0.x, a10); a10 = fmaf(q1.y, k0.y, a10);
            a11 = fmaf(q1.x, k1.x, a11); a11 = fmaf(q1.y, k1.y, a11);
        }
        ls[n0][m0]         = a00 * 0.125f;
        ls[n0][m0 + 1]     = a01 * 0.125f;
        ls[n0 + 1][m0]     = a10 * 0.125f;
        ls[n0 + 1][m0 + 1] = a11 * 0.125f;
    }
    __syncthreads();

    const int warp = tid >> 5, lane = tid & 31;
    for (int r = warp; r < 32; r += 8) {
        float v = ls[r][lane];
        float mx = v;
#pragma unroll
        for (int o = 16; o; o >>= 1) mx = fmaxf(mx, __shfl_xor_sync(0xffffffffu, mx, o));
        float ev = __expf(v - mx);
        float sm = ev;
#pragma unroll
        for (int o = 16; o; o >>= 1) sm += __shfl_xor_sync(0xffffffffu, sm, o);
        ls[r][lane] = ev / sm;
    }
    __syncthreads();

    // PV: each thread computes 2 rows x 4 cols; stores fp16 (uint2).
    {
        const int n0 = (tid >> 4) * 2;
        const int d0 = (tid & 15) * 4;
        float4 o0 = make_float4(0.f, 0.f, 0.f, 0.f);
        float4 o1 = make_float4(0.f, 0.f, 0.f, 0.f);
#pragma unroll
        for (int m = 0; m < 32; m++) {
            float p0 = ls[n0][m];
            float p1 = ls[n0 + 1][m];
            float4 v4 = *(const float4*)&vs[m][d0];
            o0.x = fmaf(p0, v4.x, o0.x); o0.y = fmaf(p0, v4.y, o0.y);
            o0.z = fmaf(p0, v4.z, o0.z); o0.w = fmaf(p0, v4.w, o0.w);
            o1.x = fmaf(p1, v4.x, o1.x); o1.y = fmaf(p1, v4.y, o1.y);
            o1.z = fmaf(p1, v4.z, o1.z); o1.w = fmaf(p1, v4.w, o1.w);
        }
        *(uint2*)&att[(long)(t0 + n0) * CDIM + h * 64 + d0] =
            make_uint2(pack_h2(o0.x, o0.y), pack_h2(o0.z, o0.w));
        *(uint2*)&att[(long)(t0 + n0 + 1) * CDIM + h * 64 + d0] =
            make_uint2(pack_h2(o1.x, o1.y), pack_h2(o1.z, o1.w));
    }
}

// ---------------------------------------------------------------------------
extern "C" void kernel_launch(void* const* d_in, const int* in_sizes, int n_in,
                              void* d_out, int out_size)
{
    (void)in_sizes; (void)n_in; (void)out_size;
    const float* x     = (const float*)d_in[0];
    const float* wqkv  = (const float*)d_in[1];
    const float* wout  = (const float*)d_in[2];
    const float* gamma = (const float*)d_in[3];
    const float* beta  = (const float*)d_in[4];
    float* out = (float*)d_out;

    float* qkv;
    __half *nh, *att_h, *wq_h, *wo_h;
    cudaGetSymbolAddress((void**)&qkv, g_qkv);
    cudaGetSymbolAddress((void**)&nh, g_nh);
    cudaGetSymbolAddress((void**)&att_h, g_att_h);
    cudaGetSymbolAddress((void**)&wq_h, g_wqkv_h);
    cudaGetSymbolAddress((void**)&wo_h, g_wout_h);

    // 0. RoPE table + weight fp16 conversion
    rope_init_kernel<<<8, 256>>>();
    w16_kernel<<<1024, 256>>>(wqkv, wout);

    // 1. LayerNorm -> g_nh (fp16, (T, C))
    ln_kernel<<<TDIM / WIN, 256>>>(x, gamma, beta, nh);

    // 2. QKV GEMM: (T, C) x (3C, C)^T -> (T, 3C) fp32
    tgemm_kernel<false><<<dim3(TDIM / 128, QKVN / 128), 128>>>(
        nh, wq_h, qkv, nullptr, TDIM, QKVN, CDIM);

    // 3. RoPE + windowed attention -> g_att_h (fp16, (T, C))
    attn_kernel<<<dim3(TDIM / WIN, NHEADS), 256>>>(att_h);

    // 4. Output GEMM + transposed residual epilogue -> d_out (C, T) fp32
    tgemm_kernel<true><<<dim3(TDIM / 128, CDIM / 128), 128>>>(
        att_h, wo_h, out, x, TDIM, CDIM, CDIM);
}